// round 6
// baseline (speedup 1.0000x reference)
#include <cuda_runtime.h>
#include <cstdint>
#include <cstdio>

// ---------------------------------------------------------------------------
// GCN_11338713662017: 3-layer GCN + mean pool + log_softmax
//   N=100000 nodes, E=1600000 edges, G=512 graphs, dims 512->128->32->2
// Index dtype (int32 vs int64) is detected on-device each call:
// JAX downgrades jnp.int64 -> int32 unless x64 is enabled, and the harness
// buffer reflects whatever setup_inputs() actually produced.
// ---------------------------------------------------------------------------

#define N_NODES  100000
#define N_EDGES  1600000
#define N_GRAPHS 512
#define F_IN     512
#define H1       128
#define H2       32
#define H3       2

// ------------------------- static device scratch ---------------------------
__device__ float g_h1[(size_t)N_NODES * H1];
__device__ float g_agg1[(size_t)N_NODES * H1];
__device__ float g_h2[(size_t)N_NODES * H2];
__device__ float g_agg2[(size_t)N_NODES * H2];
__device__ float g_h3[(size_t)N_NODES * H3];
__device__ float g_agg3[(size_t)N_NODES * H3];
__device__ float g_dinv[N_NODES];
__device__ int   g_deg[N_NODES];
__device__ float g_pool[N_GRAPHS * 2];
__device__ float g_cnt[N_GRAPHS];
__device__ int   g_src[N_EDGES];
__device__ int   g_dst[N_EDGES];
__device__ int   g_batch[N_NODES];
__device__ int   g_is64;

// ------------------------ index dtype detection -----------------------------
// Read the first 1024 uint64 words of edge_index (8KB; safe for both dtypes:
// int32 buffer is 12.8MB). Genuine int64 indices are all < N_NODES. int32
// data read as int64 packs the next index into the high word -> huge values.
__global__ void k_detect(const void* __restrict__ ei) {
    __shared__ int ok;
    if (threadIdx.x == 0) ok = 1;
    __syncthreads();
    const unsigned long long* p = (const unsigned long long*)ei;
    for (int i = threadIdx.x; i < 1024; i += blockDim.x)
        if (p[i] >= (unsigned long long)N_NODES) ok = 0;
    __syncthreads();
    if (threadIdx.x == 0) g_is64 = ok;
}

__global__ void k_zero_deg() {
    int i = blockIdx.x * blockDim.x + threadIdx.x;
    if (i < N_NODES) g_deg[i] = 0;
}

// Convert indices to int32 + count in-degrees (fused).
__global__ void k_convert(const void* __restrict__ ei, const void* __restrict__ bt) {
    int i = blockIdx.x * blockDim.x + threadIdx.x;
    const bool is64 = (g_is64 != 0);
    if (i < N_EDGES) {
        int s, d;
        if (is64) {
            s = (int)((const long long*)ei)[i];
            d = (int)((const long long*)ei)[(size_t)N_EDGES + i];
        } else {
            s = ((const int*)ei)[i];
            d = ((const int*)ei)[N_EDGES + i];
        }
        g_src[i] = s;
        g_dst[i] = d;
        atomicAdd(&g_deg[d], 1);
    }
    if (i < N_NODES)
        g_batch[i] = is64 ? (int)((const long long*)bt)[i] : ((const int*)bt)[i];
}

__global__ void k_dinv() {
    int i = blockIdx.x * blockDim.x + threadIdx.x;
    if (i < N_NODES) g_dinv[i] = rsqrtf((float)g_deg[i] + 1.0f);
}

// ------------------------------ SGEMM --------------------------------------
// C[M,N] = actA(A[M,K]) @ B[K,N].  N == BN exactly (grid.x tiles rows only).
// ACT: A element -> max(A + bias[k], 0)
template <int BM, int BN, int BK, int TM, int TN, bool ACT>
__global__ void k_sgemm(const float* __restrict__ A, const float* __restrict__ B,
                        const float* __restrict__ bias, float* __restrict__ C,
                        int M, int K, int N) {
    constexpr int NT = (BM / TM) * (BN / TN);
    __shared__ float As[BK][BM];
    __shared__ float Bs[BK][BN];

    const int tid  = threadIdx.x;
    const int row0 = blockIdx.x * BM;
    const int tx   = tid % (BN / TN);
    const int ty   = tid / (BN / TN);

    float acc[TM][TN];
#pragma unroll
    for (int m = 0; m < TM; m++)
#pragma unroll
        for (int n = 0; n < TN; n++) acc[m][n] = 0.f;

    for (int k0 = 0; k0 < K; k0 += BK) {
#pragma unroll 4
        for (int i = tid; i < BM * BK; i += NT) {
            int r = i / BK, c = i % BK;
            int gr = row0 + r;
            float v = (gr < M) ? A[(size_t)gr * K + (k0 + c)] : 0.f;
            if (ACT) v = fmaxf(v + __ldg(&bias[k0 + c]), 0.f);
            As[c][r] = v;
        }
#pragma unroll 4
        for (int i = tid; i < BK * BN; i += NT) {
            int r = i / BN, c = i % BN;
            Bs[r][c] = B[(size_t)(k0 + r) * N + c];
        }
        __syncthreads();

#pragma unroll
        for (int k = 0; k < BK; k++) {
            float ra[TM], rb[TN];
#pragma unroll
            for (int m = 0; m < TM; m++) ra[m] = As[k][ty * TM + m];
#pragma unroll
            for (int n = 0; n < TN; n++) rb[n] = Bs[k][tx * TN + n];
#pragma unroll
            for (int m = 0; m < TM; m++)
#pragma unroll
                for (int n = 0; n < TN; n++) acc[m][n] += ra[m] * rb[n];
        }
        __syncthreads();
    }

#pragma unroll
    for (int m = 0; m < TM; m++) {
        int gr = row0 + ty * TM + m;
        if (gr < M) {
#pragma unroll
            for (int n = 0; n < TN; n++)
                C[(size_t)gr * N + tx * TN + n] = acc[m][n];
        }
    }
}

// --------------------------- GEMM3 (32 -> 2) --------------------------------
__global__ void k_gemm3(const float* __restrict__ W4, const float* __restrict__ b3) {
    int i = blockIdx.x * blockDim.x + threadIdx.x;
    if (i >= N_NODES) return;
    const float4* row = (const float4*)(g_agg2 + (size_t)i * H2);
    float acc0 = 0.f, acc1 = 0.f;
#pragma unroll
    for (int q = 0; q < 8; q++) {
        float4 v = row[q];
        float vv[4] = {v.x, v.y, v.z, v.w};
#pragma unroll
        for (int j = 0; j < 4; j++) {
            int k  = q * 4 + j;
            float a = fmaxf(vv[j] + __ldg(&b3[k]), 0.f);
            acc0 += a * __ldg(&W4[k * 2 + 0]);
            acc1 += a * __ldg(&W4[k * 2 + 1]);
        }
    }
    g_h3[2 * i + 0] = acc0;
    g_h3[2 * i + 1] = acc1;
}

// ----------------------- self-loop init: agg = h * dinv^2 -------------------
template <int F>
__global__ void k_self(const float* __restrict__ h, float* __restrict__ agg) {
    unsigned idx = blockIdx.x * blockDim.x + threadIdx.x;
    unsigned total = (unsigned)N_NODES * F;
    if (idx < total) {
        int node = idx / F;
        float d = g_dinv[node];
        agg[idx] = h[idx] * d * d;
    }
}

// ----------------------------- edge scatter ---------------------------------
// F=128: one warp per edge, float4 per lane -> 512B coalesced row per warp
__global__ void k_scatter128() {
    const int lane = threadIdx.x & 31;
    const int wid  = (blockIdx.x * blockDim.x + threadIdx.x) >> 5;
    const int nw   = (gridDim.x * blockDim.x) >> 5;
    for (int e = wid; e < N_EDGES; e += nw) {
        int s = g_src[e];
        int d = g_dst[e];
        float c = g_dinv[s] * g_dinv[d];
        float4 v = ((const float4*)(g_h1 + (size_t)s * H1))[lane];
        float* a = g_agg1 + (size_t)d * H1 + lane * 4;
        atomicAdd(a + 0, v.x * c);
        atomicAdd(a + 1, v.y * c);
        atomicAdd(a + 2, v.z * c);
        atomicAdd(a + 3, v.w * c);
    }
}

// F=32: one warp per edge, one float per lane
__global__ void k_scatter32() {
    const int lane = threadIdx.x & 31;
    const int wid  = (blockIdx.x * blockDim.x + threadIdx.x) >> 5;
    const int nw   = (gridDim.x * blockDim.x) >> 5;
    for (int e = wid; e < N_EDGES; e += nw) {
        int s = g_src[e];
        int d = g_dst[e];
        float c = g_dinv[s] * g_dinv[d];
        float v = g_h2[(size_t)s * H2 + lane];
        atomicAdd(&g_agg2[(size_t)d * H2 + lane], v * c);
    }
}

// F=2: one thread per edge
__global__ void k_scatter2() {
    int e = blockIdx.x * blockDim.x + threadIdx.x;
    if (e >= N_EDGES) return;
    int s = g_src[e];
    int d = g_dst[e];
    float c = g_dinv[s] * g_dinv[d];
    atomicAdd(&g_agg3[2 * d + 0], g_h3[2 * s + 0] * c);
    atomicAdd(&g_agg3[2 * d + 1], g_h3[2 * s + 1] * c);
}

// ------------------------------- pooling ------------------------------------
__global__ void k_zero_pool() {
    int i = blockIdx.x * blockDim.x + threadIdx.x;
    if (i < N_GRAPHS) {
        g_pool[2 * i + 0] = 0.f;
        g_pool[2 * i + 1] = 0.f;
        g_cnt[i] = 0.f;
    }
}

__global__ void k_pool() {
    int i = blockIdx.x * blockDim.x + threadIdx.x;
    bool valid = (i < N_NODES);
    int g = valid ? g_batch[i] : -1;
    float v0 = valid ? g_agg3[2 * i + 0] : 0.f;
    float v1 = valid ? g_agg3[2 * i + 1] : 0.f;

    const unsigned full = 0xffffffffu;
    int g0 = __shfl_sync(full, g, 0);
    bool uni = __all_sync(full, valid && (g == g0));
    if (uni) {
#pragma unroll
        for (int off = 16; off > 0; off >>= 1) {
            v0 += __shfl_down_sync(full, v0, off);
            v1 += __shfl_down_sync(full, v1, off);
        }
        if ((threadIdx.x & 31) == 0) {
            atomicAdd(&g_pool[2 * g0 + 0], v0);
            atomicAdd(&g_pool[2 * g0 + 1], v1);
            atomicAdd(&g_cnt[g0], 32.f);
        }
    } else if (valid) {
        atomicAdd(&g_pool[2 * g + 0], v0);
        atomicAdd(&g_pool[2 * g + 1], v1);
        atomicAdd(&g_cnt[g], 1.f);
    }
}

__global__ void k_final(const float* __restrict__ b4, float* __restrict__ out) {
    int g = blockIdx.x * blockDim.x + threadIdx.x;
    if (g >= N_GRAPHS) return;
    float c  = fmaxf(g_cnt[g], 1.f);
    float s0 = g_pool[2 * g + 0] / c + b4[0];
    float s1 = g_pool[2 * g + 1] / c + b4[1];
    float m  = fmaxf(s0, s1);
    float l  = m + logf(expf(s0 - m) + expf(s1 - m));
    out[2 * g + 0] = s0 - l;
    out[2 * g + 1] = s1 - l;
}

// ------------------------------ launcher ------------------------------------
extern "C" void kernel_launch(void* const* d_in, const int* in_sizes, int n_in,
                              void* d_out, int out_size) {
    const float* x  = nullptr;
    const float* W1 = nullptr;
    const float* b1 = nullptr;
    const float* W3 = nullptr;
    const float* b3 = nullptr;
    const float* W4 = nullptr;
    const float* b4 = nullptr;
    const void*  ei = nullptr;
    const void*  bt = nullptr;

    // All input element counts are distinct -> map by size, order-agnostic.
    for (int i = 0; i < n_in; i++) {
        switch (in_sizes[i]) {
            case 51200000: x  = (const float*)d_in[i]; break;  // x [100000,512]
            case 65536:    W1 = (const float*)d_in[i]; break;  // [512,128]
            case 128:      b1 = (const float*)d_in[i]; break;
            case 4096:     W3 = (const float*)d_in[i]; break;  // [128,32]
            case 32:       b3 = (const float*)d_in[i]; break;
            case 64:       W4 = (const float*)d_in[i]; break;  // [32,2]
            case 2:        b4 = (const float*)d_in[i]; break;
            case 3200000:  ei = d_in[i]; break;                // edge_index [2,E]
            case 100000:   bt = d_in[i]; break;                // batch [N]
            default: break;                                    // num_graphs scalar
        }
    }

    float *h1p, *agg1p, *h2p, *agg2p, *h3p, *agg3p;
    cudaGetSymbolAddress((void**)&h1p,  g_h1);
    cudaGetSymbolAddress((void**)&agg1p, g_agg1);
    cudaGetSymbolAddress((void**)&h2p,  g_h2);
    cudaGetSymbolAddress((void**)&agg2p, g_agg2);
    cudaGetSymbolAddress((void**)&h3p,  g_h3);
    cudaGetSymbolAddress((void**)&agg3p, g_agg3);

    const int T = 256;

    // dtype detect -> int32 indices + degrees -> dinv
    k_detect<<<1, 256>>>(ei);
    k_zero_deg<<<(N_NODES + T - 1) / T, T>>>();
    k_convert<<<(N_EDGES + T - 1) / T, T>>>(ei, bt);
    k_dinv<<<(N_NODES + T - 1) / T, T>>>();

    // ---- layer 1: h1 = x @ W1 ; agg1 = self + norm-scatter ----
    k_sgemm<128, 128, 16, 8, 8, false>
        <<<(N_NODES + 127) / 128, 256>>>(x, W1, nullptr, h1p, N_NODES, F_IN, H1);
    k_self<H1><<<((unsigned)N_NODES * H1 + T - 1) / T, T>>>(h1p, agg1p);
    k_scatter128<<<4096, T>>>();

    // ---- layer 2: h2 = relu(agg1 + b1) @ W3 ----
    k_sgemm<128, 32, 16, 8, 2, true>
        <<<(N_NODES + 127) / 128, 256>>>(agg1p, W3, b1, h2p, N_NODES, H1, H2);
    k_self<H2><<<((unsigned)N_NODES * H2 + T - 1) / T, T>>>(h2p, agg2p);
    k_scatter32<<<4096, T>>>();

    // ---- layer 3: h3 = relu(agg2 + b3) @ W4 ----
    k_gemm3<<<(N_NODES + T - 1) / T, T>>>(W4, b3);
    k_self<H3><<<((unsigned)N_NODES * H3 + T - 1) / T, T>>>(h3p, agg3p);
    k_scatter2<<<(N_EDGES + T - 1) / T, T>>>();

    // ---- pool + log_softmax (b4 folded into finalize) ----
    k_zero_pool<<<(N_GRAPHS + T - 1) / T, T>>>();
    k_pool<<<(N_NODES + T - 1) / T, T>>>();
    k_final<<<(N_GRAPHS + T - 1) / T, T>>>(b4, (float*)d_out);
}

// round 7
// speedup vs baseline: 2.7947x; 2.7947x over previous
#include <cuda_runtime.h>
#include <cstdint>
#include <cstdio>

// ---------------------------------------------------------------------------
// GCN_11338713662017: 3-layer GCN + mean pool + log_softmax
//   N=100000 nodes, E=1600000 edges, G=512 graphs, dims 512->128->32->2
// R7 strategy: tf32 tensor-core GEMM1 + CSR-gather aggregation (no feature
// atomics), self-loop and pooling fused into the gathers.
// ---------------------------------------------------------------------------

#define N_NODES  100000
#define N_EDGES  1600000
#define N_GRAPHS 512
#define F_IN     512
#define H1       128
#define H2       32
#define H3       2

// ------------------------- static device scratch ---------------------------
__device__ float g_h1[(size_t)N_NODES * H1];
__device__ float g_agg1[(size_t)N_NODES * H1];
__device__ float g_h2[(size_t)N_NODES * H2];
__device__ float g_agg2[(size_t)N_NODES * H2];
__device__ float g_h3[(size_t)N_NODES * H3];
__device__ float g_dinv[N_NODES];
__device__ int   g_deg[N_NODES];
__device__ float g_pool[N_GRAPHS * 2];
__device__ float g_cnt[N_GRAPHS];
__device__ int   g_src[N_EDGES];
__device__ int   g_dst[N_EDGES];
__device__ int   g_batch[N_NODES];
__device__ int   g_is64;
// CSR (built per call; slot order within a node is nondeterministic but the
// aggregation is a sum -> within fp32 tolerance, same as atomic version)
__device__ int   g_off[N_NODES + 1];
__device__ int   g_cursor[N_NODES];
__device__ int   g_csrc[N_EDGES];
__device__ float g_cnorm[N_EDGES];

// ------------------------ index dtype detection -----------------------------
// int64 edge indices are all < N_NODES; int32 data read as u64 packs the next
// index into the high word -> huge values almost surely.
__global__ void k_detect(const void* __restrict__ ei) {
    __shared__ int ok;
    if (threadIdx.x == 0) ok = 1;
    __syncthreads();
    const unsigned long long* p = (const unsigned long long*)ei;
    for (int i = threadIdx.x; i < 1024; i += blockDim.x)
        if (p[i] >= (unsigned long long)N_NODES) ok = 0;
    __syncthreads();
    if (threadIdx.x == 0) g_is64 = ok;
}

__global__ void k_zero() {
    int i = blockIdx.x * blockDim.x + threadIdx.x;
    if (i < N_NODES) { g_deg[i] = 0; g_cursor[i] = 0; }
    if (i < N_GRAPHS) {
        g_pool[2 * i + 0] = 0.f; g_pool[2 * i + 1] = 0.f; g_cnt[i] = 0.f;
    }
}

// Convert indices to int32 + count in-degrees (fused).
__global__ void k_convert(const void* __restrict__ ei, const void* __restrict__ bt) {
    int i = blockIdx.x * blockDim.x + threadIdx.x;
    const bool is64 = (g_is64 != 0);
    if (i < N_EDGES) {
        int s, d;
        if (is64) {
            s = (int)((const long long*)ei)[i];
            d = (int)((const long long*)ei)[(size_t)N_EDGES + i];
        } else {
            s = ((const int*)ei)[i];
            d = ((const int*)ei)[N_EDGES + i];
        }
        g_src[i] = s;
        g_dst[i] = d;
        atomicAdd(&g_deg[d], 1);
    }
    if (i < N_NODES)
        g_batch[i] = is64 ? (int)((const long long*)bt)[i] : ((const int*)bt)[i];
}

__global__ void k_dinv() {
    int i = blockIdx.x * blockDim.x + threadIdx.x;
    if (i < N_NODES) g_dinv[i] = rsqrtf((float)g_deg[i] + 1.0f);
}

// --------------------- exclusive scan of degrees (1 block) ------------------
__global__ void k_scan() {
    __shared__ int wsum[32];
    __shared__ int s_run;
    const int tid = threadIdx.x, lane = tid & 31, w = tid >> 5;
    if (tid == 0) s_run = 0;
    __syncthreads();
    const int NQ = N_NODES / 4;   // 25000 int4 groups
    for (int base = 0; base < NQ; base += 1024) {
        int i4 = base + tid;
        int4 v = (i4 < NQ) ? ((const int4*)g_deg)[i4] : make_int4(0, 0, 0, 0);
        int t = v.x + v.y + v.z + v.w;
        int x = t;
#pragma unroll
        for (int o = 1; o < 32; o <<= 1) {
            int y = __shfl_up_sync(0xffffffffu, x, o);
            if (lane >= o) x += y;
        }
        if (lane == 31) wsum[w] = x;
        __syncthreads();
        if (w == 0) {
            int z = wsum[lane];
#pragma unroll
            for (int o = 1; o < 32; o <<= 1) {
                int y = __shfl_up_sync(0xffffffffu, z, o);
                if (lane >= o) z += y;
            }
            wsum[lane] = z;
        }
        __syncthreads();
        int excl = s_run + (w ? wsum[w - 1] : 0) + x - t;
        if (i4 < NQ) {
            g_off[4 * i4 + 0] = excl;
            g_off[4 * i4 + 1] = excl + v.x;
            g_off[4 * i4 + 2] = excl + v.x + v.y;
            g_off[4 * i4 + 3] = excl + v.x + v.y + v.z;
        }
        __syncthreads();
        if (tid == 0) s_run += wsum[31];
        __syncthreads();
    }
    if (tid == 0) g_off[N_NODES] = s_run;
}

// ------------------------ CSR fill (src + edge norm) -------------------------
__global__ void k_fill() {
    int e = blockIdx.x * blockDim.x + threadIdx.x;
    if (e >= N_EDGES) return;
    int s = g_src[e], d = g_dst[e];
    int pos = g_off[d] + atomicAdd(&g_cursor[d], 1);
    g_csrc[pos]  = s;
    g_cnorm[pos] = g_dinv[s] * g_dinv[d];
}

// ------------------------- tf32 tensor-core GEMM1 ---------------------------
// C[M,128] = A[M,512] @ B[512,128].  BM=128,BN=128,BK=32; 8 warps (4m x 2n).
__device__ __forceinline__ float f2tf32(float f) {
    uint32_t r;
    asm("cvt.rna.tf32.f32 %0, %1;" : "=r"(r) : "f"(f));
    return __uint_as_float(r);
}

__device__ __forceinline__ void mma_tf32(float* c, const uint32_t* a, const uint32_t* b) {
    asm volatile(
        "mma.sync.aligned.m16n8k8.row.col.f32.tf32.tf32.f32 "
        "{%0,%1,%2,%3}, {%4,%5,%6,%7}, {%8,%9}, {%0,%1,%2,%3};\n"
        : "+f"(c[0]), "+f"(c[1]), "+f"(c[2]), "+f"(c[3])
        : "r"(a[0]), "r"(a[1]), "r"(a[2]), "r"(a[3]), "r"(b[0]), "r"(b[1]));
}

__global__ __launch_bounds__(256) void k_gemm1_tc(const float* __restrict__ A,
                                                  const float* __restrict__ B,
                                                  float* __restrict__ C, int M) {
    // pads: A stride 36 -> frag-load bank = 4*g + t4 (conflict-free)
    //       B stride 136 -> frag-load bank = 8*t4 + g (conflict-free)
    __shared__ float As[128][36];
    __shared__ float Bs[32][136];
    const int tid  = threadIdx.x;
    const int lane = tid & 31, wid = tid >> 5;
    const int wm = wid & 3, wn = wid >> 2;      // 4 x 2 warp grid
    const int g  = lane >> 2, t4 = lane & 3;
    const int row0 = blockIdx.x * 128;

    float acc[2][8][4];
#pragma unroll
    for (int mt = 0; mt < 2; mt++)
#pragma unroll
        for (int nt = 0; nt < 8; nt++)
#pragma unroll
            for (int q = 0; q < 4; q++) acc[mt][nt][q] = 0.f;

    for (int k0 = 0; k0 < F_IN; k0 += 32) {
        // A tile: 128x32 floats = 1024 float4
#pragma unroll
        for (int l = 0; l < 4; l++) {
            int idx = tid + l * 256;
            int r = idx >> 3, c = (idx & 7) << 2;
            int gr = row0 + r;
            float4 v = (gr < M) ? *(const float4*)(A + (size_t)gr * F_IN + k0 + c)
                                : make_float4(0.f, 0.f, 0.f, 0.f);
            As[r][c + 0] = f2tf32(v.x); As[r][c + 1] = f2tf32(v.y);
            As[r][c + 2] = f2tf32(v.z); As[r][c + 3] = f2tf32(v.w);
        }
        // B tile: 32x128 floats = 1024 float4
#pragma unroll
        for (int l = 0; l < 4; l++) {
            int idx = tid + l * 256;
            int r = idx >> 5, c = (idx & 31) << 2;
            float4 v = *(const float4*)(B + (size_t)(k0 + r) * H1 + c);
            Bs[r][c + 0] = f2tf32(v.x); Bs[r][c + 1] = f2tf32(v.y);
            Bs[r][c + 2] = f2tf32(v.z); Bs[r][c + 3] = f2tf32(v.w);
        }
        __syncthreads();

#pragma unroll
        for (int kk = 0; kk < 32; kk += 8) {
            uint32_t a[2][4], b[8][2];
#pragma unroll
            for (int mt = 0; mt < 2; mt++) {
                int rb = wm * 32 + mt * 16;
                a[mt][0] = __float_as_uint(As[rb + g    ][kk + t4    ]);
                a[mt][1] = __float_as_uint(As[rb + g + 8][kk + t4    ]);
                a[mt][2] = __float_as_uint(As[rb + g    ][kk + t4 + 4]);
                a[mt][3] = __float_as_uint(As[rb + g + 8][kk + t4 + 4]);
            }
#pragma unroll
            for (int nt = 0; nt < 8; nt++) {
                int col = wn * 64 + nt * 8 + g;
                b[nt][0] = __float_as_uint(Bs[kk + t4    ][col]);
                b[nt][1] = __float_as_uint(Bs[kk + t4 + 4][col]);
            }
#pragma unroll
            for (int mt = 0; mt < 2; mt++)
#pragma unroll
                for (int nt = 0; nt < 8; nt++)
                    mma_tf32(acc[mt][nt], a[mt], b[nt]);
        }
        __syncthreads();
    }

#pragma unroll
    for (int mt = 0; mt < 2; mt++) {
        int r = row0 + wm * 32 + mt * 16 + g;
#pragma unroll
        for (int nt = 0; nt < 8; nt++) {
            int col = wn * 64 + nt * 8 + 2 * t4;
            if (r < M)
                *(float2*)(C + (size_t)r * H1 + col) = make_float2(acc[mt][nt][0], acc[mt][nt][1]);
            if (r + 8 < M)
                *(float2*)(C + (size_t)(r + 8) * H1 + col) = make_float2(acc[mt][nt][2], acc[mt][nt][3]);
        }
    }
}

// ------------------------------ SGEMM (SIMT) --------------------------------
// C[M,N] = actA(A[M,K]) @ B[K,N].  N == BN exactly.
template <int BM, int BN, int BK, int TM, int TN, bool ACT>
__global__ void k_sgemm(const float* __restrict__ A, const float* __restrict__ B,
                        const float* __restrict__ bias, float* __restrict__ C,
                        int M, int K, int N) {
    constexpr int NT = (BM / TM) * (BN / TN);
    __shared__ float As[BK][BM];
    __shared__ float Bs[BK][BN];

    const int tid  = threadIdx.x;
    const int row0 = blockIdx.x * BM;
    const int tx   = tid % (BN / TN);
    const int ty   = tid / (BN / TN);

    float acc[TM][TN];
#pragma unroll
    for (int m = 0; m < TM; m++)
#pragma unroll
        for (int n = 0; n < TN; n++) acc[m][n] = 0.f;

    for (int k0 = 0; k0 < K; k0 += BK) {
#pragma unroll 4
        for (int i = tid; i < BM * BK; i += NT) {
            int r = i / BK, c = i % BK;
            int gr = row0 + r;
            float v = (gr < M) ? A[(size_t)gr * K + (k0 + c)] : 0.f;
            if (ACT) v = fmaxf(v + __ldg(&bias[k0 + c]), 0.f);
            As[c][r] = v;
        }
#pragma unroll 4
        for (int i = tid; i < BK * BN; i += NT) {
            int r = i / BN, c = i % BN;
            Bs[r][c] = B[(size_t)(k0 + r) * N + c];
        }
        __syncthreads();

#pragma unroll
        for (int k = 0; k < BK; k++) {
            float ra[TM], rb[TN];
#pragma unroll
            for (int m = 0; m < TM; m++) ra[m] = As[k][ty * TM + m];
#pragma unroll
            for (int n = 0; n < TN; n++) rb[n] = Bs[k][tx * TN + n];
#pragma unroll
            for (int m = 0; m < TM; m++)
#pragma unroll
                for (int n = 0; n < TN; n++) acc[m][n] += ra[m] * rb[n];
        }
        __syncthreads();
    }

#pragma unroll
    for (int m = 0; m < TM; m++) {
        int gr = row0 + ty * TM + m;
        if (gr < M) {
#pragma unroll
            for (int n = 0; n < TN; n++)
                C[(size_t)gr * N + tx * TN + n] = acc[m][n];
        }
    }
}

// --------------------------- GEMM3 (32 -> 2) --------------------------------
__global__ void k_gemm3(const float* __restrict__ W4, const float* __restrict__ b3) {
    int i = blockIdx.x * blockDim.x + threadIdx.x;
    if (i >= N_NODES) return;
    const float4* row = (const float4*)(g_agg2 + (size_t)i * H2);
    float acc0 = 0.f, acc1 = 0.f;
#pragma unroll
    for (int q = 0; q < 8; q++) {
        float4 v = row[q];
        float vv[4] = {v.x, v.y, v.z, v.w};
#pragma unroll
        for (int j = 0; j < 4; j++) {
            int k  = q * 4 + j;
            float a = fmaxf(vv[j] + __ldg(&b3[k]), 0.f);
            acc0 += a * __ldg(&W4[k * 2 + 0]);
            acc1 += a * __ldg(&W4[k * 2 + 1]);
        }
    }
    g_h3[2 * i + 0] = acc0;
    g_h3[2 * i + 1] = acc1;
}

// ------------------------- CSR gather aggregation ----------------------------
// F=128: one warp per dst node; float4 per lane; self term fused.
__global__ void k_gather128() {
    const int lane = threadIdx.x & 31;
    const int d = (blockIdx.x * blockDim.x + threadIdx.x) >> 5;
    if (d >= N_NODES) return;
    float di = g_dinv[d];
    float s2 = di * di;
    float4 v = ((const float4*)(g_h1 + (size_t)d * H1))[lane];
    float4 acc  = make_float4(v.x * s2, v.y * s2, v.z * s2, v.w * s2);
    float4 acc2 = make_float4(0.f, 0.f, 0.f, 0.f);
    int e = g_off[d], eend = g_off[d + 1];
    for (; e + 2 <= eend; e += 2) {
        int   s0 = g_csrc[e],  s1 = g_csrc[e + 1];
        float c0 = g_cnorm[e], c1 = g_cnorm[e + 1];
        float4 v0 = ((const float4*)(g_h1 + (size_t)s0 * H1))[lane];
        float4 v1 = ((const float4*)(g_h1 + (size_t)s1 * H1))[lane];
        acc.x  += v0.x * c0; acc.y  += v0.y * c0; acc.z  += v0.z * c0; acc.w  += v0.w * c0;
        acc2.x += v1.x * c1; acc2.y += v1.y * c1; acc2.z += v1.z * c1; acc2.w += v1.w * c1;
    }
    if (e < eend) {
        int s0 = g_csrc[e]; float c0 = g_cnorm[e];
        float4 v0 = ((const float4*)(g_h1 + (size_t)s0 * H1))[lane];
        acc.x += v0.x * c0; acc.y += v0.y * c0; acc.z += v0.z * c0; acc.w += v0.w * c0;
    }
    acc.x += acc2.x; acc.y += acc2.y; acc.z += acc2.z; acc.w += acc2.w;
    ((float4*)(g_agg1 + (size_t)d * H1))[lane] = acc;
}

// F=32: one warp per dst node; 1 float per lane; self term fused.
__global__ void k_gather32() {
    const int lane = threadIdx.x & 31;
    const int d = (blockIdx.x * blockDim.x + threadIdx.x) >> 5;
    if (d >= N_NODES) return;
    float di = g_dinv[d];
    float acc  = g_h2[(size_t)d * H2 + lane] * di * di;
    float acc2 = 0.f;
    int e = g_off[d], eend = g_off[d + 1];
    for (; e + 2 <= eend; e += 2) {
        int   s0 = g_csrc[e],  s1 = g_csrc[e + 1];
        float c0 = g_cnorm[e], c1 = g_cnorm[e + 1];
        acc  += g_h2[(size_t)s0 * H2 + lane] * c0;
        acc2 += g_h2[(size_t)s1 * H2 + lane] * c1;
    }
    if (e < eend)
        acc += g_h2[(size_t)g_csrc[e] * H2 + lane] * g_cnorm[e];
    g_agg2[(size_t)d * H2 + lane] = acc + acc2;
}

// F=2: one warp per node, lane-parallel over edges; pooling fused.
__global__ void k_gather2_pool() {
    const int lane = threadIdx.x & 31;
    const int d = (blockIdx.x * blockDim.x + threadIdx.x) >> 5;
    if (d >= N_NODES) return;
    float a0 = 0.f, a1 = 0.f;
    int e0 = g_off[d], e1 = g_off[d + 1];
    for (int e = e0 + lane; e < e1; e += 32) {
        int s = g_csrc[e]; float c = g_cnorm[e];
        a0 += g_h3[2 * s + 0] * c;
        a1 += g_h3[2 * s + 1] * c;
    }
    const unsigned full = 0xffffffffu;
#pragma unroll
    for (int o = 16; o > 0; o >>= 1) {
        a0 += __shfl_down_sync(full, a0, o);
        a1 += __shfl_down_sync(full, a1, o);
    }
    if (lane == 0) {
        float di = g_dinv[d], s2 = di * di;
        a0 += g_h3[2 * d + 0] * s2;
        a1 += g_h3[2 * d + 1] * s2;
        int g = g_batch[d];
        atomicAdd(&g_pool[2 * g + 0], a0);
        atomicAdd(&g_pool[2 * g + 1], a1);
        atomicAdd(&g_cnt[g], 1.f);
    }
}

__global__ void k_final(const float* __restrict__ b4, float* __restrict__ out) {
    int g = blockIdx.x * blockDim.x + threadIdx.x;
    if (g >= N_GRAPHS) return;
    float c  = fmaxf(g_cnt[g], 1.f);
    float s0 = g_pool[2 * g + 0] / c + b4[0];
    float s1 = g_pool[2 * g + 1] / c + b4[1];
    float m  = fmaxf(s0, s1);
    float l  = m + logf(expf(s0 - m) + expf(s1 - m));
    out[2 * g + 0] = s0 - l;
    out[2 * g + 1] = s1 - l;
}

// ------------------------------ launcher ------------------------------------
extern "C" void kernel_launch(void* const* d_in, const int* in_sizes, int n_in,
                              void* d_out, int out_size) {
    const float* x  = nullptr;
    const float* W1 = nullptr;
    const float* b1 = nullptr;
    const float* W3 = nullptr;
    const float* b3 = nullptr;
    const float* W4 = nullptr;
    const float* b4 = nullptr;
    const void*  ei = nullptr;
    const void*  bt = nullptr;

    for (int i = 0; i < n_in; i++) {
        switch (in_sizes[i]) {
            case 51200000: x  = (const float*)d_in[i]; break;  // x [100000,512]
            case 65536:    W1 = (const float*)d_in[i]; break;  // [512,128]
            case 128:      b1 = (const float*)d_in[i]; break;
            case 4096:     W3 = (const float*)d_in[i]; break;  // [128,32]
            case 32:       b3 = (const float*)d_in[i]; break;
            case 64:       W4 = (const float*)d_in[i]; break;  // [32,2]
            case 2:        b4 = (const float*)d_in[i]; break;
            case 3200000:  ei = d_in[i]; break;                // edge_index [2,E]
            case 100000:   bt = d_in[i]; break;                // batch [N]
            default: break;                                    // num_graphs scalar
        }
    }

    float *h1p, *agg1p, *h2p;
    cudaGetSymbolAddress((void**)&h1p,  g_h1);
    cudaGetSymbolAddress((void**)&agg1p, g_agg1);
    cudaGetSymbolAddress((void**)&h2p,  g_h2);

    const int T = 256;
    const int WARP_BLOCKS = (N_NODES * 32 + T - 1) / T;   // 1 warp per node

    // --- graph preprocessing: indices -> CSR with precomputed norms ---
    k_detect<<<1, 256>>>(ei);
    k_zero<<<(N_NODES + T - 1) / T, T>>>();
    k_convert<<<(N_EDGES + T - 1) / T, T>>>(ei, bt);
    k_dinv<<<(N_NODES + T - 1) / T, T>>>();
    k_scan<<<1, 1024>>>();
    k_fill<<<(N_EDGES + T - 1) / T, T>>>();

    // --- layer 1: tf32 tensor GEMM + CSR gather (self fused) ---
    k_gemm1_tc<<<(N_NODES + 127) / 128, 256>>>(x, W1, h1p, N_NODES);
    k_gather128<<<WARP_BLOCKS, T>>>();

    // --- layer 2: SIMT GEMM (relu+b1 fused on A) + gather ---
    k_sgemm<128, 32, 16, 8, 2, true>
        <<<(N_NODES + 127) / 128, 256>>>(agg1p, W3, b1, h2p, N_NODES, H1, H2);
    k_gather32<<<WARP_BLOCKS, T>>>();

    // --- layer 3: tiny GEMM (relu+b3 fused) + gather with fused pooling ---
    k_gemm3<<<(N_NODES + T - 1) / T, T>>>(W4, b3);
    k_gather2_pool<<<WARP_BLOCKS, T>>>();

    // --- log_softmax (b4 folded in) ---
    k_final<<<(N_GRAPHS + T - 1) / T, T>>>(b4, (float*)d_out);
}

// round 12
// speedup vs baseline: 3.1294x; 1.1198x over previous
#include <cuda_runtime.h>
#include <cuda_bf16.h>
#include <cstdint>
#include <cstdio>

// ---------------------------------------------------------------------------
// GCN_11338713662017: 3-layer GCN + mean pool + log_softmax
//   N=100000 nodes, E=1600000 edges, G=512 graphs, dims 512->128->32->2
// R8: tf32 tensor GEMM1 (bf16 output) + CSR gather; CSR build runs on a
// forked stream concurrently with GEMM1 inside the captured graph.
// ---------------------------------------------------------------------------

#define N_NODES  100000
#define N_EDGES  1600000
#define N_GRAPHS 512
#define F_IN     512
#define H1       128
#define H2       32
#define H3       2

// ------------------------- static device scratch ---------------------------
__device__ __nv_bfloat162 g_h1b[(size_t)N_NODES * (H1 / 2)];  // h1 in bf16
__device__ float g_agg1[(size_t)N_NODES * H1];
__device__ float g_h2[(size_t)N_NODES * H2];
__device__ float g_agg2[(size_t)N_NODES * H2];
__device__ float g_h3[(size_t)N_NODES * H3];
__device__ float g_dinv[N_NODES];
__device__ int   g_deg[N_NODES];
__device__ float g_pool[N_GRAPHS * 2];
__device__ float g_cnt[N_GRAPHS];
__device__ int   g_src[N_EDGES];
__device__ int   g_dst[N_EDGES];
__device__ int   g_batch[N_NODES];
__device__ int   g_is64;
// CSR (rebuilt per call; slot order within a node nondeterministic, sum only)
__device__ int   g_off[N_NODES + 1];
__device__ int   g_cursor[N_NODES];
__device__ int   g_csrc[N_EDGES];
__device__ float g_cnorm[N_EDGES];

// ------------------------ index dtype detection -----------------------------
// int64 edge indices are all < N_NODES; int32 data read as u64 packs the next
// index into the high word -> huge values almost surely.
__global__ void k_detect(const void* __restrict__ ei) {
    __shared__ int ok;
    if (threadIdx.x == 0) ok = 1;
    __syncthreads();
    const unsigned long long* p = (const unsigned long long*)ei;
    for (int i = threadIdx.x; i < 1024; i += blockDim.x)
        if (p[i] >= (unsigned long long)N_NODES) ok = 0;
    __syncthreads();
    if (threadIdx.x == 0) g_is64 = ok;
}

__global__ void k_zero() {
    int i = blockIdx.x * blockDim.x + threadIdx.x;
    if (i < N_NODES) { g_deg[i] = 0; g_cursor[i] = 0; }
    if (i < N_GRAPHS) {
        g_pool[2 * i + 0] = 0.f; g_pool[2 * i + 1] = 0.f; g_cnt[i] = 0.f;
    }
}

// Convert indices to int32 + count in-degrees (fused).
__global__ void k_convert(const void* __restrict__ ei, const void* __restrict__ bt) {
    int i = blockIdx.x * blockDim.x + threadIdx.x;
    const bool is64 = (g_is64 != 0);
    if (i < N_EDGES) {
        int s, d;
        if (is64) {
            s = (int)((const long long*)ei)[i];
            d = (int)((const long long*)ei)[(size_t)N_EDGES + i];
        } else {
            s = ((const int*)ei)[i];
            d = ((const int*)ei)[N_EDGES + i];
        }
        g_src[i] = s;
        g_dst[i] = d;
        atomicAdd(&g_deg[d], 1);
    }
    if (i < N_NODES)
        g_batch[i] = is64 ? (int)((const long long*)bt)[i] : ((const int*)bt)[i];
}

__global__ void k_dinv() {
    int i = blockIdx.x * blockDim.x + threadIdx.x;
    if (i < N_NODES) g_dinv[i] = rsqrtf((float)g_deg[i] + 1.0f);
}

// --------------------- exclusive scan of degrees (1 block) ------------------
__global__ void k_scan() {
    __shared__ int wsum[32];
    __shared__ int s_run;
    const int tid = threadIdx.x, lane = tid & 31, w = tid >> 5;
    if (tid == 0) s_run = 0;
    __syncthreads();
    const int NQ = N_NODES / 4;   // 25000 int4 groups
    for (int base = 0; base < NQ; base += 1024) {
        int i4 = base + tid;
        int4 v = (i4 < NQ) ? ((const int4*)g_deg)[i4] : make_int4(0, 0, 0, 0);
        int t = v.x + v.y + v.z + v.w;
        int x = t;
#pragma unroll
        for (int o = 1; o < 32; o <<= 1) {
            int y = __shfl_up_sync(0xffffffffu, x, o);
            if (lane >= o) x += y;
        }
        if (lane == 31) wsum[w] = x;
        __syncthreads();
        if (w == 0) {
            int z = wsum[lane];
#pragma unroll
            for (int o = 1; o < 32; o <<= 1) {
                int y = __shfl_up_sync(0xffffffffu, z, o);
                if (lane >= o) z += y;
            }
            wsum[lane] = z;
        }
        __syncthreads();
        int excl = s_run + (w ? wsum[w - 1] : 0) + x - t;
        if (i4 < NQ) {
            g_off[4 * i4 + 0] = excl;
            g_off[4 * i4 + 1] = excl + v.x;
            g_off[4 * i4 + 2] = excl + v.x + v.y;
            g_off[4 * i4 + 3] = excl + v.x + v.y + v.z;
        }
        __syncthreads();
        if (tid == 0) s_run += wsum[31];
        __syncthreads();
    }
    if (tid == 0) g_off[N_NODES] = s_run;
}

// ------------------------ CSR fill (src + edge norm) -------------------------
__global__ void k_fill() {
    int e = blockIdx.x * blockDim.x + threadIdx.x;
    if (e >= N_EDGES) return;
    int s = g_src[e], d = g_dst[e];
    int pos = g_off[d] + atomicAdd(&g_cursor[d], 1);
    g_csrc[pos]  = s;
    g_cnorm[pos] = g_dinv[s] * g_dinv[d];
}

// ------------------------- tf32 tensor-core GEMM1 ---------------------------
__device__ __forceinline__ float f2tf32(float f) {
    uint32_t r;
    asm("cvt.rna.tf32.f32 %0, %1;" : "=r"(r) : "f"(f));
    return __uint_as_float(r);
}

__device__ __forceinline__ void mma_tf32(float* c, const uint32_t* a, const uint32_t* b) {
    asm volatile(
        "mma.sync.aligned.m16n8k8.row.col.f32.tf32.tf32.f32 "
        "{%0,%1,%2,%3}, {%4,%5,%6,%7}, {%8,%9}, {%0,%1,%2,%3};\n"
        : "+f"(c[0]), "+f"(c[1]), "+f"(c[2]), "+f"(c[3])
        : "r"(a[0]), "r"(a[1]), "r"(a[2]), "r"(a[3]), "r"(b[0]), "r"(b[1]));
}

// C[M,128] = A[M,512] @ B[512,128], output bf16x2. 8 warps (4m x 2n).
__global__ __launch_bounds__(256) void k_gemm1_tc(const float* __restrict__ A,
                                                  const float* __restrict__ B,
                                                  int M) {
    __shared__ float As[128][36];
    __shared__ float Bs[32][136];
    const int tid  = threadIdx.x;
    const int lane = tid & 31, wid = tid >> 5;
    const int wm = wid & 3, wn = wid >> 2;
    const int g  = lane >> 2, t4 = lane & 3;
    const int row0 = blockIdx.x * 128;

    float acc[2][8][4];
#pragma unroll
    for (int mt = 0; mt < 2; mt++)
#pragma unroll
        for (int nt = 0; nt < 8; nt++)
#pragma unroll
            for (int q = 0; q < 4; q++) acc[mt][nt][q] = 0.f;

    for (int k0 = 0; k0 < F_IN; k0 += 32) {
#pragma unroll
        for (int l = 0; l < 4; l++) {
            int idx = tid + l * 256;
            int r = idx >> 3, c = (idx & 7) << 2;
            int gr = row0 + r;
            float4 v = (gr < M) ? *(const float4*)(A + (size_t)gr * F_IN + k0 + c)
                                : make_float4(0.f, 0.f, 0.f, 0.f);
            As[r][c + 0] = f2tf32(v.x); As[r][c + 1] = f2tf32(v.y);
            As[r][c + 2] = f2tf32(v.z); As[r][c + 3] = f2tf32(v.w);
        }
#pragma unroll
        for (int l = 0; l < 4; l++) {
            int idx = tid + l * 256;
            int r = idx >> 5, c = (idx & 31) << 2;
            float4 v = *(const float4*)(B + (size_t)(k0 + r) * H1 + c);
            Bs[r][c + 0] = f2tf32(v.x); Bs[r][c + 1] = f2tf32(v.y);
            Bs[r][c + 2] = f2tf32(v.z); Bs[r][c + 3] = f2tf32(v.w);
        }
        __syncthreads();

#pragma unroll
        for (int kk = 0; kk < 32; kk += 8) {
            uint32_t a[2][4], b[8][2];
#pragma unroll
            for (int mt = 0; mt < 2; mt++) {
                int rb = wm * 32 + mt * 16;
                a[mt][0] = __float_as_uint(As[rb + g    ][kk + t4    ]);
                a[mt][1] = __float_as_uint(As[rb + g + 8][kk + t4    ]);
                a[mt][2] = __float_as_uint(As[rb + g    ][kk + t4 + 4]);
                a[mt][3] = __float_as_uint(As[rb + g + 8][kk + t4 + 4]);
            }
#pragma unroll
            for (int nt = 0; nt < 8; nt++) {
                int col = wn * 64 + nt * 8 + g;
                b[nt][0] = __float_as_uint(Bs[kk + t4    ][col]);
                b[nt][1] = __float_as_uint(Bs[kk + t4 + 4][col]);
            }
#pragma unroll
            for (int mt = 0; mt < 2; mt++)
#pragma unroll
                for (int nt = 0; nt < 8; nt++)
                    mma_tf32(acc[mt][nt], a[mt], b[nt]);
        }
        __syncthreads();
    }

#pragma unroll
    for (int mt = 0; mt < 2; mt++) {
        int r = row0 + wm * 32 + mt * 16 + g;
#pragma unroll
        for (int nt = 0; nt < 8; nt++) {
            int cp = (wn * 64 + nt * 8 + 2 * t4) >> 1;   // bf162 column index
            if (r < M)
                g_h1b[(size_t)r * (H1 / 2) + cp] =
                    __float22bfloat162_rn(make_float2(acc[mt][nt][0], acc[mt][nt][1]));
            if (r + 8 < M)
                g_h1b[(size_t)(r + 8) * (H1 / 2) + cp] =
                    __float22bfloat162_rn(make_float2(acc[mt][nt][2], acc[mt][nt][3]));
        }
    }
}

// ------------------------------ SGEMM (SIMT) --------------------------------
// C[M,N] = actA(A[M,K]) @ B[K,N].  N == BN exactly.
template <int BM, int BN, int BK, int TM, int TN, bool ACT>
__global__ void k_sgemm(const float* __restrict__ A, const float* __restrict__ B,
                        const float* __restrict__ bias, float* __restrict__ C,
                        int M, int K, int N) {
    constexpr int NT = (BM / TM) * (BN / TN);
    __shared__ float As[BK][BM];
    __shared__ float Bs[BK][BN];

    const int tid  = threadIdx.x;
    const int row0 = blockIdx.x * BM;
    const int tx   = tid % (BN / TN);
    const int ty   = tid / (BN / TN);

    float acc[TM][TN];
#pragma unroll
    for (int m = 0; m < TM; m++)
#pragma unroll
        for (int n = 0; n < TN; n++) acc[m][n] = 0.f;

    for (int k0 = 0; k0 < K; k0 += BK) {
#pragma unroll 4
        for (int i = tid; i < BM * BK; i += NT) {
            int r = i / BK, c = i % BK;
            int gr = row0 + r;
            float v = (gr < M) ? A[(size_t)gr * K + (k0 + c)] : 0.f;
            if (ACT) v = fmaxf(v + __ldg(&bias[k0 + c]), 0.f);
            As[c][r] = v;
        }
#pragma unroll 4
        for (int i = tid; i < BK * BN; i += NT) {
            int r = i / BN, c = i % BN;
            Bs[r][c] = B[(size_t)(k0 + r) * N + c];
        }
        __syncthreads();

#pragma unroll
        for (int k = 0; k < BK; k++) {
            float ra[TM], rb[TN];
#pragma unroll
            for (int m = 0; m < TM; m++) ra[m] = As[k][ty * TM + m];
#pragma unroll
            for (int n = 0; n < TN; n++) rb[n] = Bs[k][tx * TN + n];
#pragma unroll
            for (int m = 0; m < TM; m++)
#pragma unroll
                for (int n = 0; n < TN; n++) acc[m][n] += ra[m] * rb[n];
        }
        __syncthreads();
    }

#pragma unroll
    for (int m = 0; m < TM; m++) {
        int gr = row0 + ty * TM + m;
        if (gr < M) {
#pragma unroll
            for (int n = 0; n < TN; n++)
                C[(size_t)gr * N + tx * TN + n] = acc[m][n];
        }
    }
}

// --------------------------- GEMM3 (32 -> 2) --------------------------------
__global__ void k_gemm3(const float* __restrict__ W4, const float* __restrict__ b3) {
    int i = blockIdx.x * blockDim.x + threadIdx.x;
    if (i >= N_NODES) return;
    const float4* row = (const float4*)(g_agg2 + (size_t)i * H2);
    float acc0 = 0.f, acc1 = 0.f;
#pragma unroll
    for (int q = 0; q < 8; q++) {
        float4 v = row[q];
        float vv[4] = {v.x, v.y, v.z, v.w};
#pragma unroll
        for (int j = 0; j < 4; j++) {
            int k  = q * 4 + j;
            float a = fmaxf(vv[j] + __ldg(&b3[k]), 0.f);
            acc0 += a * __ldg(&W4[k * 2 + 0]);
            acc1 += a * __ldg(&W4[k * 2 + 1]);
        }
    }
    g_h3[2 * i + 0] = acc0;
    g_h3[2 * i + 1] = acc1;
}

// ------------------------- CSR gather aggregation ----------------------------
__device__ __forceinline__ float4 bf4_to_f4(uint2 u) {
    __nv_bfloat162 a = *(__nv_bfloat162*)&u.x;
    __nv_bfloat162 b = *(__nv_bfloat162*)&u.y;
    float2 fa = __bfloat1622float2(a), fb = __bfloat1622float2(b);
    return make_float4(fa.x, fa.y, fb.x, fb.y);
}

// F=128 (bf16 source): one warp per dst node; uint2 (4 features)/lane.
__global__ void k_gather128() {
    const int lane = threadIdx.x & 31;
    const int d = (blockIdx.x * blockDim.x + threadIdx.x) >> 5;
    if (d >= N_NODES) return;
    float di = g_dinv[d];
    float s2 = di * di;
    const uint2* rowd = (const uint2*)(g_h1b + (size_t)d * (H1 / 2));
    float4 v = bf4_to_f4(rowd[lane]);
    float4 acc  = make_float4(v.x * s2, v.y * s2, v.z * s2, v.w * s2);
    float4 acc2 = make_float4(0.f, 0.f, 0.f, 0.f);
    int e = g_off[d], eend = g_off[d + 1];
    for (; e + 2 <= eend; e += 2) {
        int   s0 = g_csrc[e],  s1 = g_csrc[e + 1];
        float c0 = g_cnorm[e], c1 = g_cnorm[e + 1];
        float4 v0 = bf4_to_f4(((const uint2*)(g_h1b + (size_t)s0 * (H1 / 2)))[lane]);
        float4 v1 = bf4_to_f4(((const uint2*)(g_h1b + (size_t)s1 * (H1 / 2)))[lane]);
        acc.x  += v0.x * c0; acc.y  += v0.y * c0; acc.z  += v0.z * c0; acc.w  += v0.w * c0;
        acc2.x += v1.x * c1; acc2.y += v1.y * c1; acc2.z += v1.z * c1; acc2.w += v1.w * c1;
    }
    if (e < eend) {
        int s0 = g_csrc[e]; float c0 = g_cnorm[e];
        float4 v0 = bf4_to_f4(((const uint2*)(g_h1b + (size_t)s0 * (H1 / 2)))[lane]);
        acc.x += v0.x * c0; acc.y += v0.y * c0; acc.z += v0.z * c0; acc.w += v0.w * c0;
    }
    acc.x += acc2.x; acc.y += acc2.y; acc.z += acc2.z; acc.w += acc2.w;
    ((float4*)(g_agg1 + (size_t)d * H1))[lane] = acc;
}

// F=32: one warp per dst node; 1 float per lane; self term fused.
__global__ void k_gather32() {
    const int lane = threadIdx.x & 31;
    const int d = (blockIdx.x * blockDim.x + threadIdx.x) >> 5;
    if (d >= N_NODES) return;
    float di = g_dinv[d];
    float acc  = g_h2[(size_t)d * H2 + lane] * di * di;
    float acc2 = 0.f;
    int e = g_off[d], eend = g_off[d + 1];
    for (; e + 2 <= eend; e += 2) {
        int   s0 = g_csrc[e],  s1 = g_csrc[e + 1];
        float c0 = g_cnorm[e], c1 = g_cnorm[e + 1];
        acc  += g_h2[(size_t)s0 * H2 + lane] * c0;
        acc2 += g_h2[(size_t)s1 * H2 + lane] * c1;
    }
    if (e < eend)
        acc += g_h2[(size_t)g_csrc[e] * H2 + lane] * g_cnorm[e];
    g_agg2[(size_t)d * H2 + lane] = acc + acc2;
}

// F=2: one warp per node, lane-parallel over edges; pooling fused.
__global__ void k_gather2_pool() {
    const int lane = threadIdx.x & 31;
    const int d = (blockIdx.x * blockDim.x + threadIdx.x) >> 5;
    if (d >= N_NODES) return;
    float a0 = 0.f, a1 = 0.f;
    int e0 = g_off[d], e1 = g_off[d + 1];
    for (int e = e0 + lane; e < e1; e += 32) {
        int s = g_csrc[e]; float c = g_cnorm[e];
        a0 += g_h3[2 * s + 0] * c;
        a1 += g_h3[2 * s + 1] * c;
    }
    const unsigned full = 0xffffffffu;
#pragma unroll
    for (int o = 16; o > 0; o >>= 1) {
        a0 += __shfl_down_sync(full, a0, o);
        a1 += __shfl_down_sync(full, a1, o);
    }
    if (lane == 0) {
        float di = g_dinv[d], s2 = di * di;
        a0 += g_h3[2 * d + 0] * s2;
        a1 += g_h3[2 * d + 1] * s2;
        int g = g_batch[d];
        atomicAdd(&g_pool[2 * g + 0], a0);
        atomicAdd(&g_pool[2 * g + 1], a1);
        atomicAdd(&g_cnt[g], 1.f);
    }
}

__global__ void k_final(const float* __restrict__ b4, float* __restrict__ out) {
    int g = blockIdx.x * blockDim.x + threadIdx.x;
    if (g >= N_GRAPHS) return;
    float c  = fmaxf(g_cnt[g], 1.f);
    float s0 = g_pool[2 * g + 0] / c + b4[0];
    float s1 = g_pool[2 * g + 1] / c + b4[1];
    float m  = fmaxf(s0, s1);
    float l  = m + logf(expf(s0 - m) + expf(s1 - m));
    out[2 * g + 0] = s0 - l;
    out[2 * g + 1] = s1 - l;
}

// ------------------------------ launcher ------------------------------------
extern "C" void kernel_launch(void* const* d_in, const int* in_sizes, int n_in,
                              void* d_out, int out_size) {
    const float* x  = nullptr;
    const float* W1 = nullptr;
    const float* b1 = nullptr;
    const float* W3 = nullptr;
    const float* b3 = nullptr;
    const float* W4 = nullptr;
    const float* b4 = nullptr;
    const void*  ei = nullptr;
    const void*  bt = nullptr;

    for (int i = 0; i < n_in; i++) {
        switch (in_sizes[i]) {
            case 51200000: x  = (const float*)d_in[i]; break;  // x [100000,512]
            case 65536:    W1 = (const float*)d_in[i]; break;  // [512,128]
            case 128:      b1 = (const float*)d_in[i]; break;
            case 4096:     W3 = (const float*)d_in[i]; break;  // [128,32]
            case 32:       b3 = (const float*)d_in[i]; break;
            case 64:       W4 = (const float*)d_in[i]; break;  // [32,2]
            case 2:        b4 = (const float*)d_in[i]; break;
            case 3200000:  ei = d_in[i]; break;                // edge_index [2,E]
            case 100000:   bt = d_in[i]; break;                // batch [N]
            default: break;                                    // num_graphs scalar
        }
    }

    float *agg1p, *h2p;
    cudaGetSymbolAddress((void**)&agg1p, g_agg1);
    cudaGetSymbolAddress((void**)&h2p,  g_h2);

    // Lazily created host-side resources (no device memory; work per call is
    // identical every call — same kernels, same streams, same graph shape).
    static cudaStream_t s_prep = nullptr;
    static cudaEvent_t  ev_fork = nullptr, ev_join = nullptr;
    if (!s_prep) {
        cudaStreamCreateWithFlags(&s_prep, cudaStreamNonBlocking);
        cudaEventCreateWithFlags(&ev_fork, cudaEventDisableTiming);
        cudaEventCreateWithFlags(&ev_join, cudaEventDisableTiming);
    }

    const int T = 256;
    const int WARP_BLOCKS = (N_NODES * 32 + T - 1) / T;   // 1 warp per node

    const bool fork = (s_prep != nullptr);
    cudaStream_t sp = fork ? s_prep : (cudaStream_t)0;

    if (fork) cudaEventRecord(ev_fork, 0);
    if (fork) cudaStreamWaitEvent(sp, ev_fork, 0);

    // --- prep stream: indices -> CSR with precomputed norms ---
    k_detect<<<1, 256, 0, sp>>>(ei);
    k_zero<<<(N_NODES + T - 1) / T, T, 0, sp>>>();
    k_convert<<<(N_EDGES + T - 1) / T, T, 0, sp>>>(ei, bt);
    k_dinv<<<(N_NODES + T - 1) / T, T, 0, sp>>>();
    k_scan<<<1, 1024, 0, sp>>>();
    k_fill<<<(N_EDGES + T - 1) / T, T, 0, sp>>>();

    // --- main stream: GEMM1 (tf32 tensor cores, bf16 output) ---
    k_gemm1_tc<<<(N_NODES + 127) / 128, 256>>>(x, W1, N_NODES);

    if (fork) cudaEventRecord(ev_join, sp);
    if (fork) cudaStreamWaitEvent(0, ev_join, 0);

    // --- layer 1 aggregation (self fused) ---
    k_gather128<<<WARP_BLOCKS, T>>>();

    // --- layer 2: SIMT GEMM (relu+b1 fused on A) + gather ---
    k_sgemm<128, 32, 16, 8, 2, true>
        <<<(N_NODES + 127) / 128, 256>>>(agg1p, W3, b1, h2p, N_NODES, H1, H2);
    k_gather32<<<WARP_BLOCKS, T>>>();

    // --- layer 3: tiny GEMM (relu+b3 fused) + gather with fused pooling ---
    k_gemm3<<<(N_NODES + T - 1) / T, T>>>(W4, b3);
    k_gather2_pool<<<WARP_BLOCKS, T>>>();

    // --- log_softmax (b4 folded in) ---
    k_final<<<(N_GRAPHS + T - 1) / T, T>>>(b4, (float*)d_out);
}

// round 13
// speedup vs baseline: 3.4030x; 1.0874x over previous
#include <cuda_runtime.h>
#include <cuda_bf16.h>
#include <cstdint>
#include <cstdio>

// ---------------------------------------------------------------------------
// GCN_11338713662017: 3-layer GCN + mean pool + log_softmax
//   N=100000 nodes, E=1600000 edges, G=512 graphs, dims 512->128->32->2
// R13: bf16 m16n8k16 tensor GEMM1 (prefetch double-buffered) + bf16
// intermediates everywhere + gemm3 fused into gather32. CSR build overlapped
// on a forked stream.
// ---------------------------------------------------------------------------

#define N_NODES  100000
#define N_EDGES  1600000
#define N_GRAPHS 512
#define F_IN     512
#define H1       128
#define H2       32
#define H3       2

// ------------------------- static device scratch ---------------------------
__device__ __nv_bfloat162 g_h1b[(size_t)N_NODES * (H1 / 2)];   // h1   bf16
__device__ __nv_bfloat162 g_agg1b[(size_t)N_NODES * (H1 / 2)]; // agg1 bf16
__device__ __nv_bfloat16  g_h2b[(size_t)N_NODES * H2];         // h2   bf16
__device__ float g_h3[(size_t)N_NODES * H3];
__device__ float g_dinv[N_NODES];
__device__ int   g_deg[N_NODES];
__device__ float g_pool[N_GRAPHS * 2];
__device__ float g_cnt[N_GRAPHS];
__device__ int   g_src[N_EDGES];
__device__ int   g_dst[N_EDGES];
__device__ int   g_batch[N_NODES];
__device__ int   g_is64;
// W1 packed as bf16 pairs, n-major: g_w1p[n][p] = {W1[2p][n], W1[2p+1][n]}
__device__ unsigned int g_w1p[H1 * (F_IN / 2)];
// CSR (rebuilt per call; slot order within a node nondeterministic, sum only)
__device__ int   g_off[N_NODES + 1];
__device__ int   g_cursor[N_NODES];
__device__ int   g_csrc[N_EDGES];
__device__ float g_cnorm[N_EDGES];

__device__ __forceinline__ unsigned int f2bf2(float x, float y) {
    __nv_bfloat162 h = __float22bfloat162_rn(make_float2(x, y));
    return *(unsigned int*)&h;
}

// --------------------- zero + index dtype detect (fused) ---------------------
__global__ void k_zero_detect(const void* __restrict__ ei) {
    int i = blockIdx.x * blockDim.x + threadIdx.x;
    if (i < N_NODES) { g_deg[i] = 0; g_cursor[i] = 0; }
    if (i < N_GRAPHS) {
        g_pool[2 * i + 0] = 0.f; g_pool[2 * i + 1] = 0.f; g_cnt[i] = 0.f;
    }
    if (blockIdx.x == 0) {
        // int64 indices are all < N_NODES; int32 data read as u64 packs the
        // next index into the high word -> huge values almost surely.
        __shared__ int ok;
        if (threadIdx.x == 0) ok = 1;
        __syncthreads();
        const unsigned long long* p = (const unsigned long long*)ei;
        for (int j = threadIdx.x; j < 1024; j += blockDim.x)
            if (p[j] >= (unsigned long long)N_NODES) ok = 0;
        __syncthreads();
        if (threadIdx.x == 0) g_is64 = ok;
    }
}

// Convert indices to int32 + count in-degrees (fused).
__global__ void k_convert(const void* __restrict__ ei, const void* __restrict__ bt) {
    int i = blockIdx.x * blockDim.x + threadIdx.x;
    const bool is64 = (g_is64 != 0);
    if (i < N_EDGES) {
        int s, d;
        if (is64) {
            s = (int)((const long long*)ei)[i];
            d = (int)((const long long*)ei)[(size_t)N_EDGES + i];
        } else {
            s = ((const int*)ei)[i];
            d = ((const int*)ei)[N_EDGES + i];
        }
        g_src[i] = s;
        g_dst[i] = d;
        atomicAdd(&g_deg[d], 1);
    }
    if (i < N_NODES)
        g_batch[i] = is64 ? (int)((const long long*)bt)[i] : ((const int*)bt)[i];
}

__global__ void k_dinv() {
    int i = blockIdx.x * blockDim.x + threadIdx.x;
    if (i < N_NODES) g_dinv[i] = rsqrtf((float)g_deg[i] + 1.0f);
}

// --------------------- exclusive scan of degrees (1 block) ------------------
__global__ void k_scan() {
    __shared__ int wsum[32];
    __shared__ int s_run;
    const int tid = threadIdx.x, lane = tid & 31, w = tid >> 5;
    if (tid == 0) s_run = 0;
    __syncthreads();
    const int NQ = N_NODES / 4;
    for (int base = 0; base < NQ; base += 1024) {
        int i4 = base + tid;
        int4 v = (i4 < NQ) ? ((const int4*)g_deg)[i4] : make_int4(0, 0, 0, 0);
        int t = v.x + v.y + v.z + v.w;
        int x = t;
#pragma unroll
        for (int o = 1; o < 32; o <<= 1) {
            int y = __shfl_up_sync(0xffffffffu, x, o);
            if (lane >= o) x += y;
        }
        if (lane == 31) wsum[w] = x;
        __syncthreads();
        if (w == 0) {
            int z = wsum[lane];
#pragma unroll
            for (int o = 1; o < 32; o <<= 1) {
                int y = __shfl_up_sync(0xffffffffu, z, o);
                if (lane >= o) z += y;
            }
            wsum[lane] = z;
        }
        __syncthreads();
        int excl = s_run + (w ? wsum[w - 1] : 0) + x - t;
        if (i4 < NQ) {
            g_off[4 * i4 + 0] = excl;
            g_off[4 * i4 + 1] = excl + v.x;
            g_off[4 * i4 + 2] = excl + v.x + v.y;
            g_off[4 * i4 + 3] = excl + v.x + v.y + v.z;
        }
        __syncthreads();
        if (tid == 0) s_run += wsum[31];
        __syncthreads();
    }
    if (tid == 0) g_off[N_NODES] = s_run;
}

// ------------------------ CSR fill (src + edge norm) -------------------------
__global__ void k_fill() {
    int e = blockIdx.x * blockDim.x + threadIdx.x;
    if (e >= N_EDGES) return;
    int s = g_src[e], d = g_dst[e];
    int pos = g_off[d] + atomicAdd(&g_cursor[d], 1);
    g_csrc[pos]  = s;
    g_cnorm[pos] = g_dinv[s] * g_dinv[d];
}

// ------------------ W1 -> bf16 pair pack: g_w1p[n][p] ------------------------
__global__ void k_packW1(const float* __restrict__ W1) {
    int i = blockIdx.x * blockDim.x + threadIdx.x;     // 32768 = 256 p x 128 n
    if (i >= H1 * (F_IN / 2)) return;
    int p = i >> 7, n = i & 127;                        // reads coalesced on n
    float a = W1[(size_t)(2 * p) * H1 + n];
    float b = W1[(size_t)(2 * p + 1) * H1 + n];
    g_w1p[n * (F_IN / 2) + p] = f2bf2(a, b);
}

// ------------------------- bf16 tensor-core GEMM1 ---------------------------
__device__ __forceinline__ void mma_bf16(float* c, const unsigned int* a,
                                         const unsigned int* b) {
    asm volatile(
        "mma.sync.aligned.m16n8k16.row.col.f32.bf16.bf16.f32 "
        "{%0,%1,%2,%3}, {%4,%5,%6,%7}, {%8,%9}, {%0,%1,%2,%3};\n"
        : "+f"(c[0]), "+f"(c[1]), "+f"(c[2]), "+f"(c[3])
        : "r"(a[0]), "r"(a[1]), "r"(a[2]), "r"(a[3]), "r"(b[0]), "r"(b[1]));
}

// C[M,128] = A[M,512] @ W1, output bf16x2 to g_h1b. 8 warps (4m x 2n).
// Smem holds bf16 PAIRS (uint): As2[r][pair] stride 20 (frag loads bank-
// perfect: g*20+t4 spans all 32 banks), Bs2[n][pair] stride 20 likewise.
__global__ __launch_bounds__(256) void k_gemm1_bf16(const float* __restrict__ A,
                                                    int M) {
    __shared__ __align__(16) unsigned int As2[128][20];
    __shared__ __align__(16) unsigned int Bs2[128][20];
    const int tid  = threadIdx.x;
    const int lane = tid & 31, wid = tid >> 5;
    const int wm = wid & 3, wn = wid >> 2;
    const int g  = lane >> 2, t4 = lane & 3;
    const int row0 = blockIdx.x * 128;

    float acc[2][8][4];
#pragma unroll
    for (int mt = 0; mt < 2; mt++)
#pragma unroll
        for (int nt = 0; nt < 8; nt++)
#pragma unroll
            for (int q = 0; q < 4; q++) acc[mt][nt][q] = 0.f;

    float4 pa[4];   // A prefetch: 4 float4 per thread
    uint2  pb[4];   // B prefetch: 4 uint2 per thread (pairs from g_w1p)

    auto loadA = [&](int k0) {
#pragma unroll
        for (int l = 0; l < 4; l++) {
            int idx = tid + l * 256;              // 1024 float4s: 128r x 8c4
            int r = idx >> 3, c4 = idx & 7;
            int gr = row0 + r;
            pa[l] = (gr < M) ? *(const float4*)(A + (size_t)gr * F_IN + k0 + c4 * 4)
                             : make_float4(0.f, 0.f, 0.f, 0.f);
        }
    };
    auto loadB = [&](int k0) {
        int pbase = k0 >> 1;
#pragma unroll
        for (int l = 0; l < 4; l++) {
            int idx2 = tid + l * 256;             // 1024 uint2: 128n x 8q2
            int n = idx2 >> 3, q2 = idx2 & 7;
            pb[l] = *(const uint2*)(g_w1p + n * (F_IN / 2) + pbase + q2 * 2);
        }
    };
    auto storeAB = [&]() {
#pragma unroll
        for (int l = 0; l < 4; l++) {
            int idx = tid + l * 256;
            int r = idx >> 3, c4 = idx & 7;
            As2[r][c4 * 2 + 0] = f2bf2(pa[l].x, pa[l].y);
            As2[r][c4 * 2 + 1] = f2bf2(pa[l].z, pa[l].w);
            int n = idx >> 3, q2 = idx & 7;
            *(uint2*)&Bs2[n][q2 * 2] = pb[l];
        }
    };

    loadA(0); loadB(0);
    storeAB();
    __syncthreads();

    for (int k0 = 0; k0 < F_IN; k0 += 32) {
        const bool has_next = (k0 + 32 < F_IN);
        if (has_next) { loadA(k0 + 32); loadB(k0 + 32); }

#pragma unroll
        for (int s = 0; s < 2; s++) {             // two k16 steps per tile
            unsigned int a[2][4], b[8][2];
#pragma unroll
            for (int mt = 0; mt < 2; mt++) {
                int rb = wm * 32 + mt * 16;
                a[mt][0] = As2[rb + g    ][s * 8 + t4    ];
                a[mt][1] = As2[rb + g + 8][s * 8 + t4    ];
                a[mt][2] = As2[rb + g    ][s * 8 + t4 + 4];
                a[mt][3] = As2[rb + g + 8][s * 8 + t4 + 4];
            }
#pragma unroll
            for (int nt = 0; nt < 8; nt++) {
                int col = wn * 64 + nt * 8 + g;
                b[nt][0] = Bs2[col][s * 8 + t4    ];
                b[nt][1] = Bs2[col][s * 8 + t4 + 4];
            }
#pragma unroll
            for (int mt = 0; mt < 2; mt++)
#pragma unroll
                for (int nt = 0; nt < 8; nt++)
                    mma_bf16(acc[mt][nt], a[mt], b[nt]);
        }
        __syncthreads();
        if (has_next) {
            storeAB();
            __syncthreads();
        }
    }

#pragma unroll
    for (int mt = 0; mt < 2; mt++) {
        int r = row0 + wm * 32 + mt * 16 + g;
#pragma unroll
        for (int nt = 0; nt < 8; nt++) {
            int cp = (wn * 64 + nt * 8 + 2 * t4) >> 1;
            if (r < M)
                g_h1b[(size_t)r * (H1 / 2) + cp] =
                    __float22bfloat162_rn(make_float2(acc[mt][nt][0], acc[mt][nt][1]));
            if (r + 8 < M)
                g_h1b[(size_t)(r + 8) * (H1 / 2) + cp] =
                    __float22bfloat162_rn(make_float2(acc[mt][nt][2], acc[mt][nt][3]));
        }
    }
}

// ------------------------- CSR gather aggregation ----------------------------
__device__ __forceinline__ float4 bf4_to_f4(uint2 u) {
    __nv_bfloat162 a = *(__nv_bfloat162*)&u.x;
    __nv_bfloat162 b = *(__nv_bfloat162*)&u.y;
    float2 fa = __bfloat1622float2(a), fb = __bfloat1622float2(b);
    return make_float4(fa.x, fa.y, fb.x, fb.y);
}

// F=128 (bf16 in/out): one warp per dst node; uint2 (4 features)/lane;
// unroll-4 for MLP. Self term fused. Writes bf16 agg1.
__global__ void k_gather128() {
    const int lane = threadIdx.x & 31;
    const int d = (blockIdx.x * blockDim.x + threadIdx.x) >> 5;
    if (d >= N_NODES) return;
    float di = g_dinv[d];
    float s2 = di * di;
    float4 v = bf4_to_f4(((const uint2*)(g_h1b + (size_t)d * (H1 / 2)))[lane]);
    float4 a0 = make_float4(v.x * s2, v.y * s2, v.z * s2, v.w * s2);
    float4 a1 = make_float4(0.f, 0.f, 0.f, 0.f);
    float4 a2 = make_float4(0.f, 0.f, 0.f, 0.f);
    float4 a3 = make_float4(0.f, 0.f, 0.f, 0.f);
    int e = g_off[d], eend = g_off[d + 1];
    for (; e + 4 <= eend; e += 4) {
        int   s0c = g_csrc[e],   s1c = g_csrc[e + 1];
        int   s2c = g_csrc[e + 2], s3c = g_csrc[e + 3];
        float c0 = g_cnorm[e],     c1 = g_cnorm[e + 1];
        float c2 = g_cnorm[e + 2], c3 = g_cnorm[e + 3];
        float4 v0 = bf4_to_f4(((const uint2*)(g_h1b + (size_t)s0c * (H1 / 2)))[lane]);
        float4 v1 = bf4_to_f4(((const uint2*)(g_h1b + (size_t)s1c * (H1 / 2)))[lane]);
        float4 v2 = bf4_to_f4(((const uint2*)(g_h1b + (size_t)s2c * (H1 / 2)))[lane]);
        float4 v3 = bf4_to_f4(((const uint2*)(g_h1b + (size_t)s3c * (H1 / 2)))[lane]);
        a0.x += v0.x * c0; a0.y += v0.y * c0; a0.z += v0.z * c0; a0.w += v0.w * c0;
        a1.x += v1.x * c1; a1.y += v1.y * c1; a1.z += v1.z * c1; a1.w += v1.w * c1;
        a2.x += v2.x * c2; a2.y += v2.y * c2; a2.z += v2.z * c2; a2.w += v2.w * c2;
        a3.x += v3.x * c3; a3.y += v3.y * c3; a3.z += v3.z * c3; a3.w += v3.w * c3;
    }
    for (; e < eend; e++) {
        int sc = g_csrc[e]; float c = g_cnorm[e];
        float4 v0 = bf4_to_f4(((const uint2*)(g_h1b + (size_t)sc * (H1 / 2)))[lane]);
        a0.x += v0.x * c; a0.y += v0.y * c; a0.z += v0.z * c; a0.w += v0.w * c;
    }
    a0.x += a1.x + a2.x + a3.x; a0.y += a1.y + a2.y + a3.y;
    a0.z += a1.z + a2.z + a3.z; a0.w += a1.w + a2.w + a3.w;
    uint2 out;
    out.x = f2bf2(a0.x, a0.y);
    out.y = f2bf2(a0.z, a0.w);
    ((uint2*)(g_agg1b + (size_t)d * (H1 / 2)))[lane] = out;
}

// ------------------------------ SGEMM2 (SIMT) --------------------------------
// h2(bf16) = relu(agg1b(bf16) + b1) @ W3.  BM=128,BN=32,BK=16,TM=8,TN=2.
__global__ void k_sgemm2(const __nv_bfloat16* __restrict__ A,
                         const float* __restrict__ B,
                         const float* __restrict__ bias, int M) {
    constexpr int BM = 128, BN = 32, BK = 16, TM = 8, TN = 2;
    constexpr int NT = (BM / TM) * (BN / TN);
    __shared__ float As[BK][BM];
    __shared__ float Bs[BK][BN];

    const int tid  = threadIdx.x;
    const int row0 = blockIdx.x * BM;
    const int tx   = tid % (BN / TN);
    const int ty   = tid / (BN / TN);

    float acc[TM][TN];
#pragma unroll
    for (int m = 0; m < TM; m++)
#pragma unroll
        for (int n = 0; n < TN; n++) acc[m][n] = 0.f;

    for (int k0 = 0; k0 < H1; k0 += BK) {
#pragma unroll 4
        for (int i = tid; i < BM * BK; i += NT) {
            int r = i / BK, c = i % BK;
            int gr = row0 + r;
            float v = (gr < M) ? __bfloat162float(A[(size_t)gr * H1 + (k0 + c)]) : 0.f;
            As[c][r] = fmaxf(v + __ldg(&bias[k0 + c]), 0.f);
        }
#pragma unroll 2
        for (int i = tid; i < BK * BN; i += NT) {
            int r = i / BN, c = i % BN;
            Bs[r][c] = B[(size_t)(k0 + r) * BN + c];
        }
        __syncthreads();

#pragma unroll
        for (int k = 0; k < BK; k++) {
            float ra[TM], rb[TN];
#pragma unroll
            for (int m = 0; m < TM; m++) ra[m] = As[k][ty * TM + m];
#pragma unroll
            for (int n = 0; n < TN; n++) rb[n] = Bs[k][tx * TN + n];
#pragma unroll
            for (int m = 0; m < TM; m++)
#pragma unroll
                for (int n = 0; n < TN; n++) acc[m][n] += ra[m] * rb[n];
        }
        __syncthreads();
    }

#pragma unroll
    for (int m = 0; m < TM; m++) {
        int gr = row0 + ty * TM + m;
        if (gr < M)   // cols tx*2, tx*2+1 packed into one bf16x2 store
            ((unsigned int*)(g_h2b + (size_t)gr * H2))[tx] = f2bf2(acc[m][0], acc[m][1]);
    }
}

// --------------- gather32 + gemm3 fused: h3 = Â relu(...)@W4 -----------------
// One warp per dst node; lane = feature j. agg2 never materialized.
__global__ void k_gather32_gemm3(const float* __restrict__ W4,
                                 const float* __restrict__ b3) {
    const int lane = threadIdx.x & 31;
    const int d = (blockIdx.x * blockDim.x + threadIdx.x) >> 5;
    if (d >= N_NODES) return;
    float di = g_dinv[d];
    float acc  = __bfloat162float(g_h2b[(size_t)d * H2 + lane]) * di * di;
    float acc2 = 0.f;
    int e = g_off[d], eend = g_off[d + 1];
    for (; e + 2 <= eend; e += 2) {
        int   s0 = g_csrc[e],  s1 = g_csrc[e + 1];
        float c0 = g_cnorm[e], c1 = g_cnorm[e + 1];
        acc  += __bfloat162float(g_h2b[(size_t)s0 * H2 + lane]) * c0;
        acc2 += __bfloat162float(g_h2b[(size_t)s1 * H2 + lane]) * c1;
    }
    if (e < eend)
        acc += __bfloat162float(g_h2b[(size_t)g_csrc[e] * H2 + lane]) * g_cnorm[e];
    acc += acc2;
    // fused gemm3: a = relu(acc + b3[j]); h3[d] += a * W4[j][:]
    float a  = fmaxf(acc + __ldg(&b3[lane]), 0.f);
    float p0 = a * __ldg(&W4[2 * lane + 0]);
    float p1 = a * __ldg(&W4[2 * lane + 1]);
    const unsigned full = 0xffffffffu;
#pragma unroll
    for (int o = 16; o > 0; o >>= 1) {
        p0 += __shfl_down_sync(full, p0, o);
        p1 += __shfl_down_sync(full, p1, o);
    }
    if (lane == 0) {
        g_h3[2 * d + 0] = p0;
        g_h3[2 * d + 1] = p1;
    }
}

// F=2: one warp per node, lane-parallel over edges; pooling fused.
__global__ void k_gather2_pool() {
    const int lane = threadIdx.x & 31;
    const int d = (blockIdx.x * blockDim.x + threadIdx.x) >> 5;
    if (d >= N_NODES) return;
    float a0 = 0.f, a1 = 0.f;
    int e0 = g_off[d], e1 = g_off[d + 1];
    for (int e = e0 + lane; e < e1; e += 32) {
        int s = g_csrc[e]; float c = g_cnorm[e];
        a0 += g_h3[2 * s + 0] * c;
        a1 += g_h3[2 * s + 1] * c;
    }
    const unsigned full = 0xffffffffu;
#pragma unroll
    for (int o = 16; o > 0; o >>= 1) {
        a0 += __shfl_down_sync(full, a0, o);
        a1 += __shfl_down_sync(full, a1, o);
    }
    if (lane == 0) {
        float di = g_dinv[d], s2 = di * di;
        a0 += g_h3[2 * d + 0] * s2;
        a1 += g_h3[2 * d + 1] * s2;
        int g = g_batch[d];
        atomicAdd(&g_pool[2 * g + 0], a0);
        atomicAdd(&g_pool[2 * g + 1], a1);
        atomicAdd(&g_cnt[g], 1.f);
    }
}

__global__ void k_final(const float* __restrict__ b4, float* __restrict__ out) {
    int g = blockIdx.x * blockDim.x + threadIdx.x;
    if (g >= N_GRAPHS) return;
    float c  = fmaxf(g_cnt[g], 1.f);
    float s0 = g_pool[2 * g + 0] / c + b4[0];
    float s1 = g_pool[2 * g + 1] / c + b4[1];
    float m  = fmaxf(s0, s1);
    float l  = m + logf(expf(s0 - m) + expf(s1 - m));
    out[2 * g + 0] = s0 - l;
    out[2 * g + 1] = s1 - l;
}

// ------------------------------ launcher ------------------------------------
extern "C" void kernel_launch(void* const* d_in, const int* in_sizes, int n_in,
                              void* d_out, int out_size) {
    const float* x  = nullptr;
    const float* W1 = nullptr;
    const float* b1 = nullptr;
    const float* W3 = nullptr;
    const float* b3 = nullptr;
    const float* W4 = nullptr;
    const float* b4 = nullptr;
    const void*  ei = nullptr;
    const void*  bt = nullptr;

    for (int i = 0; i < n_in; i++) {
        switch (in_sizes[i]) {
            case 51200000: x  = (const float*)d_in[i]; break;  // x [100000,512]
            case 65536:    W1 = (const float*)d_in[i]; break;  // [512,128]
            case 128:      b1 = (const float*)d_in[i]; break;
            case 4096:     W3 = (const float*)d_in[i]; break;  // [128,32]
            case 32:       b3 = (const float*)d_in[i]; break;
            case 64:       W4 = (const float*)d_in[i]; break;  // [32,2]
            case 2:        b4 = (const float*)d_in[i]; break;
            case 3200000:  ei = d_in[i]; break;                // edge_index [2,E]
            case 100000:   bt = d_in[i]; break;                // batch [N]
            default: break;                                    // num_graphs scalar
        }
    }

    __nv_bfloat16* agg1p;
    cudaGetSymbolAddress((void**)&agg1p, g_agg1b);

    // Lazily created host-side resources (no device memory).
    static cudaStream_t s_prep = nullptr;
    static cudaEvent_t  ev_fork = nullptr, ev_join = nullptr;
    if (!s_prep) {
        cudaStreamCreateWithFlags(&s_prep, cudaStreamNonBlocking);
        cudaEventCreateWithFlags(&ev_fork, cudaEventDisableTiming);
        cudaEventCreateWithFlags(&ev_join, cudaEventDisableTiming);
    }

    const int T = 256;
    const int WARP_BLOCKS = (N_NODES * 32 + T - 1) / T;   // 1 warp per node

    cudaEventRecord(ev_fork, 0);
    cudaStreamWaitEvent(s_prep, ev_fork, 0);

    // --- prep stream: indices -> CSR with precomputed norms ---
    k_zero_detect<<<(N_NODES + T - 1) / T, T, 0, s_prep>>>(ei);
    k_convert<<<(N_EDGES + T - 1) / T, T, 0, s_prep>>>(ei, bt);
    k_dinv<<<(N_NODES + T - 1) / T, T, 0, s_prep>>>();
    k_scan<<<1, 1024, 0, s_prep>>>();
    k_fill<<<(N_EDGES + T - 1) / T, T, 0, s_prep>>>();
    cudaEventRecord(ev_join, s_prep);

    // --- main stream: pack W1, then bf16 tensor GEMM1 ---
    k_packW1<<<(H1 * (F_IN / 2) + T - 1) / T, T>>>(W1);
    k_gemm1_bf16<<<(N_NODES + 127) / 128, 256>>>(x, N_NODES);

    cudaStreamWaitEvent(0, ev_join, 0);

    // --- layer 1 aggregation (self fused, bf16 in/out) ---
    k_gather128<<<WARP_BLOCKS, T>>>();

    // --- layer 2: SIMT GEMM (relu+b1 fused on A, bf16 A and C) ---
    k_sgemm2<<<(N_NODES + 127) / 128, 256>>>(agg1p, W3, b1, N_NODES);

    // --- layer 3 fused: gather32 + relu+b3 + W4 -> h3 ---
    k_gather32_gemm3<<<WARP_BLOCKS, T>>>(W4, b3);

    // --- final aggregation + pooling fused ---
    k_gather2_pool<<<WARP_BLOCKS, T>>>();

    // --- log_softmax (b4 folded in) ---
    k_final<<<(N_GRAPHS + T - 1) / T, T>>>(b4, (float*)d_out);
}

// round 16
// speedup vs baseline: 4.3295x; 1.2723x over previous
#include <cuda_runtime.h>
#include <cuda_bf16.h>
#include <cstdint>
#include <cstdio>

// ---------------------------------------------------------------------------
// GCN_11338713662017: 3-layer GCN + mean pool + log_softmax
//   N=100000 nodes, E=1600000 edges, G=512 graphs, dims 512->128->32->2
// R14: parallel 3-phase degree scan (was 46us single-block) + bf16 tensor-core
// sgemm2. bf16 m16n8k16 GEMM1, bf16 intermediates, gemm3 fused into gather32,
// CSR build overlapped on a forked stream.
// ---------------------------------------------------------------------------

#define N_NODES  100000
#define N_EDGES  1600000
#define N_GRAPHS 512
#define F_IN     512
#define H1       128
#define H2       32
#define H3       2
#define SCAN_BLOCKS ((N_NODES + 1023) / 1024)   // 98

// ------------------------- static device scratch ---------------------------
__device__ __nv_bfloat162 g_h1b[(size_t)N_NODES * (H1 / 2)];   // h1   bf16
__device__ __nv_bfloat162 g_agg1b[(size_t)N_NODES * (H1 / 2)]; // agg1 bf16
__device__ __nv_bfloat16  g_h2b[(size_t)N_NODES * H2];         // h2   bf16
__device__ float g_h3[(size_t)N_NODES * H3];
__device__ float g_dinv[N_NODES];
__device__ int   g_deg[N_NODES];
__device__ float g_pool[N_GRAPHS * 2];
__device__ float g_cnt[N_GRAPHS];
__device__ int   g_src[N_EDGES];
__device__ int   g_dst[N_EDGES];
__device__ int   g_batch[N_NODES];
__device__ int   g_is64;
// packed bf16-pair weights, n-major: g_w1p[n][p] = {W[2p][n], W[2p+1][n]}
__device__ __align__(16) unsigned int g_w1p[H1 * (F_IN / 2)];
__device__ __align__(16) unsigned int g_w3p[H2 * (H1 / 2)];
// CSR (rebuilt per call; slot order within a node nondeterministic, sum only)
__device__ int   g_off[N_NODES + 1];
__device__ int   g_cursor[N_NODES];
__device__ int   g_csrc[N_EDGES];
__device__ float g_cnorm[N_EDGES];
// scan partials
__device__ int   g_bsum[128];
__device__ int   g_bpre[128];

__device__ __forceinline__ unsigned int f2bf2(float x, float y) {
    __nv_bfloat162 h = __float22bfloat162_rn(make_float2(x, y));
    return *(unsigned int*)&h;
}

// --------------------- zero + index dtype detect (fused) ---------------------
__global__ void k_zero_detect(const void* __restrict__ ei) {
    int i = blockIdx.x * blockDim.x + threadIdx.x;
    if (i < N_NODES) { g_deg[i] = 0; g_cursor[i] = 0; }
    if (i < N_GRAPHS) {
        g_pool[2 * i + 0] = 0.f; g_pool[2 * i + 1] = 0.f; g_cnt[i] = 0.f;
    }
    if (blockIdx.x == 0) {
        // int64 indices are all < N_NODES; int32 data read as u64 packs the
        // next index into the high word -> huge values almost surely.
        __shared__ int ok;
        if (threadIdx.x == 0) ok = 1;
        __syncthreads();
        const unsigned long long* p = (const unsigned long long*)ei;
        for (int j = threadIdx.x; j < 1024; j += blockDim.x)
            if (p[j] >= (unsigned long long)N_NODES) ok = 0;
        __syncthreads();
        if (threadIdx.x == 0) g_is64 = ok;
    }
}

// Convert indices to int32 + count in-degrees (fused).
__global__ void k_convert(const void* __restrict__ ei, const void* __restrict__ bt) {
    int i = blockIdx.x * blockDim.x + threadIdx.x;
    const bool is64 = (g_is64 != 0);
    if (i < N_EDGES) {
        int s, d;
        if (is64) {
            s = (int)((const long long*)ei)[i];
            d = (int)((const long long*)ei)[(size_t)N_EDGES + i];
        } else {
            s = ((const int*)ei)[i];
            d = ((const int*)ei)[N_EDGES + i];
        }
        g_src[i] = s;
        g_dst[i] = d;
        atomicAdd(&g_deg[d], 1);
    }
    if (i < N_NODES)
        g_batch[i] = is64 ? (int)((const long long*)bt)[i] : ((const int*)bt)[i];
}

__global__ void k_dinv() {
    int i = blockIdx.x * blockDim.x + threadIdx.x;
    if (i < N_NODES) g_dinv[i] = rsqrtf((float)g_deg[i] + 1.0f);
}

// ------------------- parallel 3-phase exclusive scan of deg -------------------
// phase 1: per-block (1024 elems) exclusive scan into g_off + block sum
__global__ void k_scan1() {
    __shared__ int wsum[32];
    const int tid = threadIdx.x, lane = tid & 31, w = tid >> 5;
    int i = blockIdx.x * 1024 + tid;
    int v = (i < N_NODES) ? g_deg[i] : 0;
    int x = v;
#pragma unroll
    for (int o = 1; o < 32; o <<= 1) {
        int y = __shfl_up_sync(0xffffffffu, x, o);
        if (lane >= o) x += y;
    }
    if (lane == 31) wsum[w] = x;
    __syncthreads();
    if (w == 0) {
        int z = wsum[lane];
#pragma unroll
        for (int o = 1; o < 32; o <<= 1) {
            int y = __shfl_up_sync(0xffffffffu, z, o);
            if (lane >= o) z += y;
        }
        wsum[lane] = z;
    }
    __syncthreads();
    if (i < N_NODES) g_off[i] = (w ? wsum[w - 1] : 0) + x - v;
    if (tid == 0) g_bsum[blockIdx.x] = wsum[31];
}

// phase 2: scan the 98 block sums (1 block, 128 threads)
__global__ void k_scan2() {
    __shared__ int wsum[4];
    const int tid = threadIdx.x, lane = tid & 31, w = tid >> 5;
    int v = (tid < SCAN_BLOCKS) ? g_bsum[tid] : 0;
    int x = v;
#pragma unroll
    for (int o = 1; o < 32; o <<= 1) {
        int y = __shfl_up_sync(0xffffffffu, x, o);
        if (lane >= o) x += y;
    }
    if (lane == 31) wsum[w] = x;
    __syncthreads();
    if (tid == 0) {
        int r = 0;
#pragma unroll
        for (int q = 0; q < 4; q++) { int t = wsum[q]; wsum[q] = r; r += t; }
        g_off[N_NODES] = r;     // total
    }
    __syncthreads();
    if (tid < SCAN_BLOCKS) g_bpre[tid] = wsum[w] + x - v;
}

// phase 3: add block prefixes
__global__ void k_scan3() {
    int i = blockIdx.x * 1024 + threadIdx.x;
    if (i < N_NODES) g_off[i] += g_bpre[blockIdx.x];
}

// ------------------------ CSR fill (src + edge norm) -------------------------
__global__ void k_fill() {
    int e = blockIdx.x * blockDim.x + threadIdx.x;
    if (e >= N_EDGES) return;
    int s = g_src[e], d = g_dst[e];
    int pos = g_off[d] + atomicAdd(&g_cursor[d], 1);
    g_csrc[pos]  = s;
    g_cnorm[pos] = g_dinv[s] * g_dinv[d];
}

// ------------- W1/W3 -> bf16 pair pack (n-major), one kernel ------------------
__global__ void k_packW(const float* __restrict__ W1, const float* __restrict__ W3) {
    int i = blockIdx.x * blockDim.x + threadIdx.x;
    if (i < H1 * (F_IN / 2)) {                    // W1: 32768
        int p = i >> 7, n = i & 127;
        g_w1p[n * (F_IN / 2) + p] =
            f2bf2(W1[(size_t)(2 * p) * H1 + n], W1[(size_t)(2 * p + 1) * H1 + n]);
    } else {
        int j = i - H1 * (F_IN / 2);              // W3: 2048 = 64p x 32n
        if (j < H2 * (H1 / 2)) {
            int p = j >> 5, n = j & 31;
            g_w3p[n * (H1 / 2) + p] =
                f2bf2(W3[(size_t)(2 * p) * H2 + n], W3[(size_t)(2 * p + 1) * H2 + n]);
        }
    }
}

// ------------------------- bf16 tensor-core GEMM1 ---------------------------
__device__ __forceinline__ void mma_bf16(float* c, const unsigned int* a,
                                         const unsigned int* b) {
    asm volatile(
        "mma.sync.aligned.m16n8k16.row.col.f32.bf16.bf16.f32 "
        "{%0,%1,%2,%3}, {%4,%5,%6,%7}, {%8,%9}, {%0,%1,%2,%3};\n"
        : "+f"(c[0]), "+f"(c[1]), "+f"(c[2]), "+f"(c[3])
        : "r"(a[0]), "r"(a[1]), "r"(a[2]), "r"(a[3]), "r"(b[0]), "r"(b[1]));
}

// C[M,128] = A[M,512] @ W1, output bf16x2 to g_h1b. 8 warps (4m x 2n).
__global__ __launch_bounds__(256) void k_gemm1_bf16(const float* __restrict__ A,
                                                    int M) {
    __shared__ __align__(16) unsigned int As2[128][20];
    __shared__ __align__(16) unsigned int Bs2[128][20];
    const int tid  = threadIdx.x;
    const int lane = tid & 31, wid = tid >> 5;
    const int wm = wid & 3, wn = wid >> 2;
    const int g  = lane >> 2, t4 = lane & 3;
    const int row0 = blockIdx.x * 128;

    float acc[2][8][4];
#pragma unroll
    for (int mt = 0; mt < 2; mt++)
#pragma unroll
        for (int nt = 0; nt < 8; nt++)
#pragma unroll
            for (int q = 0; q < 4; q++) acc[mt][nt][q] = 0.f;

    float4 pa[4];
    uint2  pb[4];

    auto loadA = [&](int k0) {
#pragma unroll
        for (int l = 0; l < 4; l++) {
            int idx = tid + l * 256;
            int r = idx >> 3, c4 = idx & 7;
            int gr = row0 + r;
            pa[l] = (gr < M) ? *(const float4*)(A + (size_t)gr * F_IN + k0 + c4 * 4)
                             : make_float4(0.f, 0.f, 0.f, 0.f);
        }
    };
    auto loadB = [&](int k0) {
        int pbase = k0 >> 1;
#pragma unroll
        for (int l = 0; l < 4; l++) {
            int idx2 = tid + l * 256;
            int n = idx2 >> 3, q2 = idx2 & 7;
            pb[l] = *(const uint2*)(g_w1p + n * (F_IN / 2) + pbase + q2 * 2);
        }
    };
    auto storeAB = [&]() {
#pragma unroll
        for (int l = 0; l < 4; l++) {
            int idx = tid + l * 256;
            int r = idx >> 3, c4 = idx & 7;
            As2[r][c4 * 2 + 0] = f2bf2(pa[l].x, pa[l].y);
            As2[r][c4 * 2 + 1] = f2bf2(pa[l].z, pa[l].w);
            *(uint2*)&Bs2[r][c4 * 2] = pb[l];
        }
    };

    loadA(0); loadB(0);
    storeAB();
    __syncthreads();

    for (int k0 = 0; k0 < F_IN; k0 += 32) {
        const bool has_next = (k0 + 32 < F_IN);
        if (has_next) { loadA(k0 + 32); loadB(k0 + 32); }

#pragma unroll
        for (int s = 0; s < 2; s++) {
            unsigned int a[2][4], b[8][2];
#pragma unroll
            for (int mt = 0; mt < 2; mt++) {
                int rb = wm * 32 + mt * 16;
                a[mt][0] = As2[rb + g    ][s * 8 + t4    ];
                a[mt][1] = As2[rb + g + 8][s * 8 + t4    ];
                a[mt][2] = As2[rb + g    ][s * 8 + t4 + 4];
                a[mt][3] = As2[rb + g + 8][s * 8 + t4 + 4];
            }
#pragma unroll
            for (int nt = 0; nt < 8; nt++) {
                int col = wn * 64 + nt * 8 + g;
                b[nt][0] = Bs2[col][s * 8 + t4    ];
                b[nt][1] = Bs2[col][s * 8 + t4 + 4];
            }
#pragma unroll
            for (int mt = 0; mt < 2; mt++)
#pragma unroll
                for (int nt = 0; nt < 8; nt++)
                    mma_bf16(acc[mt][nt], a[mt], b[nt]);
        }
        __syncthreads();
        if (has_next) {
            storeAB();
            __syncthreads();
        }
    }

#pragma unroll
    for (int mt = 0; mt < 2; mt++) {
        int r = row0 + wm * 32 + mt * 16 + g;
#pragma unroll
        for (int nt = 0; nt < 8; nt++) {
            int cp = (wn * 64 + nt * 8 + 2 * t4) >> 1;
            if (r < M)
                g_h1b[(size_t)r * (H1 / 2) + cp] =
                    __float22bfloat162_rn(make_float2(acc[mt][nt][0], acc[mt][nt][1]));
            if (r + 8 < M)
                g_h1b[(size_t)(r + 8) * (H1 / 2) + cp] =
                    __float22bfloat162_rn(make_float2(acc[mt][nt][2], acc[mt][nt][3]));
        }
    }
}

// ------------------------- CSR gather aggregation ----------------------------
__device__ __forceinline__ float4 bf4_to_f4(uint2 u) {
    __nv_bfloat162 a = *(__nv_bfloat162*)&u.x;
    __nv_bfloat162 b = *(__nv_bfloat162*)&u.y;
    float2 fa = __bfloat1622float2(a), fb = __bfloat1622float2(b);
    return make_float4(fa.x, fa.y, fb.x, fb.y);
}

// F=128 (bf16 in/out): one warp per dst node; uint2 (4 features)/lane.
__global__ void k_gather128() {
    const int lane = threadIdx.x & 31;
    const int d = (blockIdx.x * blockDim.x + threadIdx.x) >> 5;
    if (d >= N_NODES) return;
    float di = g_dinv[d];
    float s2 = di * di;
    float4 v = bf4_to_f4(((const uint2*)(g_h1b + (size_t)d * (H1 / 2)))[lane]);
    float4 a0 = make_float4(v.x * s2, v.y * s2, v.z * s2, v.w * s2);
    float4 a1 = make_float4(0.f, 0.f, 0.f, 0.f);
    float4 a2 = make_float4(0.f, 0.f, 0.f, 0.f);
    float4 a3 = make_float4(0.f, 0.f, 0.f, 0.f);
    int e = g_off[d], eend = g_off[d + 1];
    for (; e + 4 <= eend; e += 4) {
        int   s0c = g_csrc[e],     s1c = g_csrc[e + 1];
        int   s2c = g_csrc[e + 2], s3c = g_csrc[e + 3];
        float c0 = g_cnorm[e],     c1 = g_cnorm[e + 1];
        float c2 = g_cnorm[e + 2], c3 = g_cnorm[e + 3];
        float4 v0 = bf4_to_f4(((const uint2*)(g_h1b + (size_t)s0c * (H1 / 2)))[lane]);
        float4 v1 = bf4_to_f4(((const uint2*)(g_h1b + (size_t)s1c * (H1 / 2)))[lane]);
        float4 v2 = bf4_to_f4(((const uint2*)(g_h1b + (size_t)s2c * (H1 / 2)))[lane]);
        float4 v3 = bf4_to_f4(((const uint2*)(g_h1b + (size_t)s3c * (H1 / 2)))[lane]);
        a0.x += v0.x * c0; a0.y += v0.y * c0; a0.z += v0.z * c0; a0.w += v0.w * c0;
        a1.x += v1.x * c1; a1.y += v1.y * c1; a1.z += v1.z * c1; a1.w += v1.w * c1;
        a2.x += v2.x * c2; a2.y += v2.y * c2; a2.z += v2.z * c2; a2.w += v2.w * c2;
        a3.x += v3.x * c3; a3.y += v3.y * c3; a3.z += v3.z * c3; a3.w += v3.w * c3;
    }
    for (; e < eend; e++) {
        int sc = g_csrc[e]; float c = g_cnorm[e];
        float4 v0 = bf4_to_f4(((const uint2*)(g_h1b + (size_t)sc * (H1 / 2)))[lane]);
        a0.x += v0.x * c; a0.y += v0.y * c; a0.z += v0.z * c; a0.w += v0.w * c;
    }
    a0.x += a1.x + a2.x + a3.x; a0.y += a1.y + a2.y + a3.y;
    a0.z += a1.z + a2.z + a3.z; a0.w += a1.w + a2.w + a3.w;
    uint2 out;
    out.x = f2bf2(a0.x, a0.y);
    out.y = f2bf2(a0.z, a0.w);
    ((uint2*)(g_agg1b + (size_t)d * (H1 / 2)))[lane] = out;
}

// ---------------------- bf16 tensor-core GEMM2 -------------------------------
// h2(bf16) = relu(agg1b + b1) @ W3.  One K pass (K=128). 8 warps (4m x 2n).
__global__ __launch_bounds__(256) void k_gemm2_tc(const float* __restrict__ bias,
                                                  int M) {
    __shared__ __align__(16) unsigned int As2[128][68];
    __shared__ __align__(16) unsigned int Bs2[32][68];
    const int tid  = threadIdx.x;
    const int lane = tid & 31, wid = tid >> 5;
    const int wm = wid & 3, wn = wid >> 2;
    const int g  = lane >> 2, t4 = lane & 3;
    const int row0 = blockIdx.x * 128;

    // A tile: 4096 uint2 (rows x 32 uint2), bias+relu fused, repacked bf16
#pragma unroll
    for (int l = 0; l < 16; l++) {
        int idx = tid + l * 256;
        int r = idx >> 5, q2 = idx & 31;
        int gr = row0 + r;
        uint2 u = (gr < M) ? ((const uint2*)(g_agg1b + (size_t)gr * (H1 / 2)))[q2]
                           : make_uint2(0u, 0u);
        float4 f = bf4_to_f4(u);
        int k = q2 * 4;
        float r0 = fmaxf(f.x + __ldg(&bias[k + 0]), 0.f);
        float r1 = fmaxf(f.y + __ldg(&bias[k + 1]), 0.f);
        float r2 = fmaxf(f.z + __ldg(&bias[k + 2]), 0.f);
        float r3 = fmaxf(f.w + __ldg(&bias[k + 3]), 0.f);
        As2[r][q2 * 2 + 0] = f2bf2(r0, r1);
        As2[r][q2 * 2 + 1] = f2bf2(r2, r3);
    }
    // B tile: 1024 uint2 (32 n x 32 uint2)
#pragma unroll
    for (int l = 0; l < 4; l++) {
        int idx = tid + l * 256;
        int n = idx >> 5, q2 = idx & 31;
        *(uint2*)&Bs2[n][q2 * 2] = *(const uint2*)(g_w3p + n * (H1 / 2) + q2 * 2);
    }
    __syncthreads();

    float acc[2][2][4];
#pragma unroll
    for (int mt = 0; mt < 2; mt++)
#pragma unroll
        for (int nt = 0; nt < 2; nt++)
#pragma unroll
            for (int q = 0; q < 4; q++) acc[mt][nt][q] = 0.f;

#pragma unroll
    for (int s = 0; s < 8; s++) {                 // 8 k16 steps (K=128)
        unsigned int a[2][4], b[2][2];
#pragma unroll
        for (int mt = 0; mt < 2; mt++) {
            int rb = wm * 32 + mt * 16;
            a[mt][0] = As2[rb + g    ][s * 8 + t4    ];
            a[mt][1] = As2[rb + g + 8][s * 8 + t4    ];
            a[mt][2] = As2[rb + g    ][s * 8 + t4 + 4];
            a[mt][3] = As2[rb + g + 8][s * 8 + t4 + 4];
        }
#pragma unroll
        for (int nt = 0; nt < 2; nt++) {
            int col = wn * 16 + nt * 8 + g;
            b[nt][0] = Bs2[col][s * 8 + t4    ];
            b[nt][1] = Bs2[col][s * 8 + t4 + 4];
        }
#pragma unroll
        for (int mt = 0; mt < 2; mt++)
#pragma unroll
            for (int nt = 0; nt < 2; nt++)
                mma_bf16(acc[mt][nt], a[mt], b[nt]);
    }

#pragma unroll
    for (int mt = 0; mt < 2; mt++) {
        int r = row0 + wm * 32 + mt * 16 + g;
#pragma unroll
        for (int nt = 0; nt < 2; nt++) {
            int cp = wn * 8 + nt * 4 + t4;        // (wn*16+nt*8+2*t4)/2
            if (r < M)
                ((unsigned int*)(g_h2b + (size_t)r * H2))[cp] =
                    f2bf2(acc[mt][nt][0], acc[mt][nt][1]);
            if (r + 8 < M)
                ((unsigned int*)(g_h2b + (size_t)(r + 8) * H2))[cp] =
                    f2bf2(acc[mt][nt][2], acc[mt][nt][3]);
        }
    }
}

// --------------- gather32 + gemm3 fused: h3 = Â relu(...)@W4 -----------------
__global__ void k_gather32_gemm3(const float* __restrict__ W4,
                                 const float* __restrict__ b3) {
    const int lane = threadIdx.x & 31;
    const int d = (blockIdx.x * blockDim.x + threadIdx.x) >> 5;
    if (d >= N_NODES) return;
    float di = g_dinv[d];
    float acc  = __bfloat162float(g_h2b[(size_t)d * H2 + lane]) * di * di;
    float acc2 = 0.f;
    int e = g_off[d], eend = g_off[d + 1];
    for (; e + 2 <= eend; e += 2) {
        int   s0 = g_csrc[e],  s1 = g_csrc[e + 1];
        float c0 = g_cnorm[e], c1 = g_cnorm[e + 1];
        acc  += __bfloat162float(g_h2b[(size_t)s0 * H2 + lane]) * c0;
        acc2 += __bfloat162float(g_h2b[(size_t)s1 * H2 + lane]) * c1;
    }
    if (e < eend)
        acc += __bfloat162float(g_h2b[(size_t)g_csrc[e] * H2 + lane]) * g_cnorm[e];
    acc += acc2;
    float a  = fmaxf(acc + __ldg(&b3[lane]), 0.f);
    float p0 = a * __ldg(&W4[2 * lane + 0]);
    float p1 = a * __ldg(&W4[2 * lane + 1]);
    const unsigned full = 0xffffffffu;
#pragma unroll
    for (int o = 16; o > 0; o >>= 1) {
        p0 += __shfl_down_sync(full, p0, o);
        p1 += __shfl_down_sync(full, p1, o);
    }
    if (lane == 0) {
        g_h3[2 * d + 0] = p0;
        g_h3[2 * d + 1] = p1;
    }
}

// F=2: one warp per node, lane-parallel over edges; pooling fused.
__global__ void k_gather2_pool() {
    const int lane = threadIdx.x & 31;
    const int d = (blockIdx.x * blockDim.x + threadIdx.x) >> 5;
    if (d >= N_NODES) return;
    float a0 = 0.f, a1 = 0.f;
    int e0 = g_off[d], e1 = g_off[d + 1];
    for (int e = e0 + lane; e < e1; e += 32) {
        int s = g_csrc[e]; float c = g_cnorm[e];
        a0 += g_h3[2 * s + 0] * c;
        a1 += g_h3[2 * s + 1] * c;
    }
    const unsigned full = 0xffffffffu;
#pragma unroll
    for (int o = 16; o > 0; o >>= 1) {
        a0 += __shfl_down_sync(full, a0, o);
        a1 += __shfl_down_sync(full, a1, o);
    }
    if (lane == 0) {
        float di = g_dinv[d], s2 = di * di;
        a0 += g_h3[2 * d + 0] * s2;
        a1 += g_h3[2 * d + 1] * s2;
        int g = g_batch[d];
        atomicAdd(&g_pool[2 * g + 0], a0);
        atomicAdd(&g_pool[2 * g + 1], a1);
        atomicAdd(&g_cnt[g], 1.f);
    }
}

__global__ void k_final(const float* __restrict__ b4, float* __restrict__ out) {
    int g = blockIdx.x * blockDim.x + threadIdx.x;
    if (g >= N_GRAPHS) return;
    float c  = fmaxf(g_cnt[g], 1.f);
    float s0 = g_pool[2 * g + 0] / c + b4[0];
    float s1 = g_pool[2 * g + 1] / c + b4[1];
    float m  = fmaxf(s0, s1);
    float l  = m + logf(expf(s0 - m) + expf(s1 - m));
    out[2 * g + 0] = s0 - l;
    out[2 * g + 1] = s1 - l;
}

// ------------------------------ launcher ------------------------------------
extern "C" void kernel_launch(void* const* d_in, const int* in_sizes, int n_in,
                              void* d_out, int out_size) {
    const float* x  = nullptr;
    const float* W1 = nullptr;
    const float* b1 = nullptr;
    const float* W3 = nullptr;
    const float* b3 = nullptr;
    const float* W4 = nullptr;
    const float* b4 = nullptr;
    const void*  ei = nullptr;
    const void*  bt = nullptr;

    for (int i = 0; i < n_in; i++) {
        switch (in_sizes[i]) {
            case 51200000: x  = (const float*)d_in[i]; break;  // x [100000,512]
            case 65536:    W1 = (const float*)d_in[i]; break;  // [512,128]
            case 128:      b1 = (const float*)d_in[i]; break;
            case 4096:     W3 = (const float*)d_in[i]; break;  // [128,32]
            case 32:       b3 = (const float*)d_in[i]; break;
            case 64:       W4 = (const float*)d_in[i]; break;  // [32,2]
            case 2:        b4 = (const float*)d_in[i]; break;
            case 3200000:  ei = d_in[i]; break;                // edge_index [2,E]
            case 100000:   bt = d_in[i]; break;                // batch [N]
            default: break;                                    // num_graphs scalar
        }
    }

    // Lazily created host-side resources (no device memory).
    static cudaStream_t s_prep = nullptr;
    static cudaEvent_t  ev_fork = nullptr, ev_join = nullptr;
    if (!s_prep) {
        cudaStreamCreateWithFlags(&s_prep, cudaStreamNonBlocking);
        cudaEventCreateWithFlags(&ev_fork, cudaEventDisableTiming);
        cudaEventCreateWithFlags(&ev_join, cudaEventDisableTiming);
    }

    const int T = 256;
    const int WARP_BLOCKS = (N_NODES * 32 + T - 1) / T;   // 1 warp per node

    cudaEventRecord(ev_fork, 0);
    cudaStreamWaitEvent(s_prep, ev_fork, 0);

    // --- prep stream: indices -> CSR with precomputed norms ---
    k_zero_detect<<<(N_NODES + T - 1) / T, T, 0, s_prep>>>(ei);
    k_convert<<<(N_EDGES + T - 1) / T, T, 0, s_prep>>>(ei, bt);
    k_dinv<<<(N_NODES + T - 1) / T, T, 0, s_prep>>>();
    k_scan1<<<SCAN_BLOCKS, 1024, 0, s_prep>>>();
    k_scan2<<<1, 128, 0, s_prep>>>();
    k_scan3<<<SCAN_BLOCKS, 1024, 0, s_prep>>>();
    k_fill<<<(N_EDGES + T - 1) / T, T, 0, s_prep>>>();
    cudaEventRecord(ev_join, s_prep);

    // --- main stream: pack weights, then bf16 tensor GEMM1 ---
    k_packW<<<(H1 * (F_IN / 2) + H2 * (H1 / 2) + T - 1) / T, T>>>(W1, W3);
    k_gemm1_bf16<<<(N_NODES + 127) / 128, 256>>>(x, N_NODES);

    cudaStreamWaitEvent(0, ev_join, 0);

    // --- layer 1 aggregation (self fused, bf16 in/out) ---
    k_gather128<<<WARP_BLOCKS, T>>>();

    // --- layer 2: bf16 tensor GEMM (relu+b1 fused on A) ---
    k_gemm2_tc<<<(N_NODES + 127) / 128, 256>>>(b1, N_NODES);

    // --- layer 3 fused: gather32 + relu+b3 + W4 -> h3 ---
    k_gather32_gemm3<<<WARP_BLOCKS, T>>>(W4, b3);

    // --- final aggregation + pooling fused ---
    k_gather2_pool<<<WARP_BLOCKS, T>>>();

    // --- log_softmax (b4 folded in) ---
    k_final<<<(N_GRAPHS + T - 1) / T, T>>>(b4, (float*)d_out);
}